// round 14
// baseline (speedup 1.0000x reference)
#include <cuda_runtime.h>
#include <cuda_fp16.h>
#include <math.h>

typedef unsigned long long ull;

// ---------------- fp16 MMA helpers -------------------------------------------------
__device__ __forceinline__ unsigned h2pk(float a, float b) {
  __half2 h = __floats2half2_rn(a, b);
  return *(unsigned*)&h;
}
__device__ __forceinline__ void mma_f16(float* c, const unsigned* a, unsigned b0, unsigned b1) {
  asm volatile(
      "mma.sync.aligned.m16n8k16.row.col.f32.f16.f16.f32 "
      "{%0,%1,%2,%3},{%4,%5,%6,%7},{%8,%9},{%0,%1,%2,%3};"
      : "+f"(c[0]), "+f"(c[1]), "+f"(c[2]), "+f"(c[3])
      : "r"(a[0]), "r"(a[1]), "r"(a[2]), "r"(a[3]), "r"(b0), "r"(b1));
}
__device__ __forceinline__ float gelu_exact(float a) {
  return 0.5f * a * (1.f + erff(a * 0.70710678118654752f));
}

// ---------------- static device scratch --------------------------------------------
__device__ float g_pos[64 * 64];
__device__ __half g_qh[3 * 1024 * 4096];
__device__ __half g_ql[3 * 1024 * 4096];
__device__ __half g_kh[3 * 1024 * 4096];
__device__ __half g_kl[3 * 1024 * 4096];
__device__ __half g_vt[3 * 1024 * 4096];
__device__ float g_xres[192 * 65536];
__device__ __half g_hbh[768 * 65536];
__device__ __half g_gbh[384 * 65536];
// packed fp16 weight fragments: [ntile][kit16][lane] -> (b0 | b1<<32)
__device__ ull g_wp_in[96 * 12 * 32];     // ff_in  (K=192, N=768)
__device__ ull g_wp_out[24 * 24 * 32];    // ff_out (K=384, N=192)
__device__ ull g_wp11[3 * 8 * 12 * 32];   // me_w11 (K=192, N=64)
__device__ ull g_wp12[3 * 8 * 12 * 32];   // me_w12
__device__ ull g_wp2[3 * 8 * 4 * 32];     // me_w2  (K=64,  N=64)
__device__ ull g_wpqkv[24 * 4 * 32];      // w_qkv  (K=64,  N=192)
__device__ ull g_wp192[24 * 12 * 32];     // conv11 (K=192, N=192)

// ---------------- K0a: sine positional encoding ------------------------------------
__global__ void kpos() {
  int n = threadIdx.x;
  int i = n >> 3, j = n & 7;
  double scale = 6.283185307179586476925286766559;
  double yv = (double)(i + 1) / (8.0 + 1e-6) * scale;
  double xv = (double)(j + 1) / (8.0 + 1e-6) * scale;
  for (int c = 0; c < 64; c++) {
    double base = (c < 32) ? yv : xv;
    int k = (c < 32) ? c : (c - 32);
    double dt = pow(10000.0, (double)(k >> 1) / 16.0);
    double v = base / dt;
    g_pos[n * 64 + c] = (float)(((k & 1) == 0) ? sin(v) : cos(v));
  }
}

// ---------------- K0b: fp16 fragment packing ---------------------------------------
__global__ void kpack(const float* __restrict__ c11, const float* __restrict__ ffin,
                      const float* __restrict__ ffout, const float* __restrict__ w11,
                      const float* __restrict__ w12, const float* __restrict__ w2,
                      const float* __restrict__ wqkv) {
  int idx = blockIdx.x * 256 + threadIdx.x;
  int lane = idx & 31;
  if (idx < 36864) {  // wp_in [96][12][32], src [o=768][k=192]
    int kit = (idx >> 5) % 12, nt = idx / 384;
    int o = nt * 8 + (lane >> 2), k0 = kit * 16 + (lane & 3) * 2;
    unsigned b0 = h2pk(ffin[o * 192 + k0], ffin[o * 192 + k0 + 1]);
    unsigned b1 = h2pk(ffin[o * 192 + k0 + 8], ffin[o * 192 + k0 + 9]);
    g_wp_in[idx] = (ull)b0 | ((ull)b1 << 32);
  }
  if (idx < 18432) {  // wp_out [24][24][32], src [o=192][k=384]
    int kit = (idx >> 5) % 24, nt = idx / 768;
    int o = nt * 8 + (lane >> 2), k0 = kit * 16 + (lane & 3) * 2;
    unsigned b0 = h2pk(ffout[o * 384 + k0], ffout[o * 384 + k0 + 1]);
    unsigned b1 = h2pk(ffout[o * 384 + k0 + 8], ffout[o * 384 + k0 + 9]);
    g_wp_out[idx] = (ull)b0 | ((ull)b1 << 32);
  }
  if (idx < 9216) {  // wp11/wp12 [3][8][12][32], src [e][k=192][f=64]
    int e = idx / 3072, r = idx % 3072;
    int kit = (r >> 5) % 12, nt = r / 384;
    int f = nt * 8 + (lane >> 2), k0 = kit * 16 + (lane & 3) * 2;
    const float* Wa = w11 + e * 12288;
    const float* Wb = w12 + e * 12288;
    unsigned a0 = h2pk(Wa[k0 * 64 + f], Wa[(k0 + 1) * 64 + f]);
    unsigned a1 = h2pk(Wa[(k0 + 8) * 64 + f], Wa[(k0 + 9) * 64 + f]);
    g_wp11[idx] = (ull)a0 | ((ull)a1 << 32);
    unsigned c0 = h2pk(Wb[k0 * 64 + f], Wb[(k0 + 1) * 64 + f]);
    unsigned c1 = h2pk(Wb[(k0 + 8) * 64 + f], Wb[(k0 + 9) * 64 + f]);
    g_wp12[idx] = (ull)c0 | ((ull)c1 << 32);
  }
  if (idx < 3072) {  // wp2 [3][8][4][32], src [e][k=64][f=64]
    int e = idx / 1024, r = idx % 1024;
    int kit = (r >> 5) % 4, nt = r / 128;
    int f = nt * 8 + (lane >> 2), k0 = kit * 16 + (lane & 3) * 2;
    const float* Wa = w2 + e * 4096;
    unsigned b0 = h2pk(Wa[k0 * 64 + f], Wa[(k0 + 1) * 64 + f]);
    unsigned b1 = h2pk(Wa[(k0 + 8) * 64 + f], Wa[(k0 + 9) * 64 + f]);
    g_wp2[idx] = (ull)b0 | ((ull)b1 << 32);
  }
  if (idx < 3072) {  // wpqkv [24][4][32], src [k=64][n=192]
    int kit = (idx >> 5) % 4, nt = idx / 128;
    int n = nt * 8 + (lane >> 2), k0 = kit * 16 + (lane & 3) * 2;
    unsigned b0 = h2pk(wqkv[k0 * 192 + n], wqkv[(k0 + 1) * 192 + n]);
    unsigned b1 = h2pk(wqkv[(k0 + 8) * 192 + n], wqkv[(k0 + 9) * 192 + n]);
    g_wpqkv[idx] = (ull)b0 | ((ull)b1 << 32);
  }
  if (idx < 9216) {  // wp192 [24][12][32], src [o=192][k=192]
    int kit = (idx >> 5) % 12, nt = idx / 384;
    int o = nt * 8 + (lane >> 2), k0 = kit * 16 + (lane & 3) * 2;
    unsigned b0 = h2pk(c11[o * 192 + k0], c11[o * 192 + k0 + 1]);
    unsigned b1 = h2pk(c11[o * 192 + k0 + 8], c11[o * 192 + k0 + 9]);
    g_wp192[idx] = (ull)b0 | ((ull)b1 << 32);
  }
}

// ---------------- K1: shift+window + LN1 + pos + QKV GEMM (fp16 MMA) ---------------
__global__ void k1_qkv(const float* __restrict__ x, const float* __restrict__ ln1w,
                       const float* __restrict__ ln1b) {
  extern __shared__ float sm1[];
  float* sx = sm1;
  unsigned* snT = (unsigned*)(sm1 + 4160);
  float* sout = sm1;
  __shared__ float smean[64], srstd[64];
  int blk = blockIdx.x;
  int e = blk >> 10, wwin = blk & 1023;
  int wh = wwin >> 5, ww = wwin & 31;
  int t = threadIdx.x;
  for (int idx = t; idx < 4096; idx += 256) {
    int c = idx >> 6, n = idx & 63;
    int i = n >> 3, j = n & 7;
    int h0 = (wh * 8 + i + 4) & 255;
    int w0 = (ww * 8 + j + 4) & 255;
    sx[n * 65 + c] = x[((e * 64 + c) * 256 + h0) * 256 + w0];
  }
  __syncthreads();
  if (t < 64) {
    int n = t;
    float m = 0.f;
#pragma unroll
    for (int c = 0; c < 64; c++) m += sx[n * 65 + c];
    m *= (1.f / 64.f);
    float v = 0.f;
#pragma unroll
    for (int c = 0; c < 64; c++) { float d = sx[n * 65 + c] - m; v += d * d; }
    v *= (1.f / 64.f);
    smean[n] = m;
    srstd[n] = rsqrtf(v + 1e-5f);
  }
  __syncthreads();
  for (int idx = t; idx < 2048; idx += 256) {
    int n = idx >> 5, kk = idx & 31;
    int c = kk * 2;
    float v0 = (sx[n * 65 + c] - smean[n]) * srstd[n] * ln1w[c] + ln1b[c] + g_pos[n * 64 + c];
    float v1 = (sx[n * 65 + c + 1] - smean[n]) * srstd[n] * ln1w[c + 1] + ln1b[c + 1] + g_pos[n * 64 + c + 1];
    snT[n * 36 + kk] = h2pk(v0, v1);
  }
  __syncthreads();
  int wa = t >> 5, lane = t & 31;
  int rq = lane >> 2, acol = lane & 3, ccol0 = 2 * acol;
  float acc[3][4][4];
#pragma unroll
  for (int j = 0; j < 3; j++)
#pragma unroll
    for (int mt = 0; mt < 4; mt++)
#pragma unroll
      for (int r = 0; r < 4; r++) acc[j][mt][r] = 0.f;
  for (int kit = 0; kit < 4; kit++) {
    unsigned A[4][4];
#pragma unroll
    for (int mt = 0; mt < 4; mt++) {
      int r = mt * 16 + rq;
      A[mt][0] = snT[r * 36 + kit * 8 + acol];
      A[mt][1] = snT[(r + 8) * 36 + kit * 8 + acol];
      A[mt][2] = snT[r * 36 + kit * 8 + acol + 4];
      A[mt][3] = snT[(r + 8) * 36 + kit * 8 + acol + 4];
    }
#pragma unroll
    for (int j = 0; j < 3; j++) {
      ull wv = g_wpqkv[((wa * 3 + j) * 4 + kit) * 32 + lane];
#pragma unroll
      for (int mt = 0; mt < 4; mt++)
        mma_f16(acc[j][mt], A[mt], (unsigned)wv, (unsigned)(wv >> 32));
    }
  }
  __syncthreads();
#pragma unroll
  for (int j = 0; j < 3; j++) {
    int jc = (wa * 3 + j) * 8 + ccol0;
#pragma unroll
    for (int mt = 0; mt < 4; mt++) {
      int r0 = mt * 16 + rq;
      sout[jc * 65 + r0] = acc[j][mt][0];
      sout[(jc + 1) * 65 + r0] = acc[j][mt][1];
      sout[jc * 65 + r0 + 8] = acc[j][mt][2];
      sout[(jc + 1) * 65 + r0 + 8] = acc[j][mt][3];
    }
  }
  __syncthreads();
  int wb = e * 1024 + wwin;
  // q/k: hi/lo fp16 split, half2-vectorized (channel pairs)
  for (int idx = t; idx < 4096; idx += 256) {
    int ch2 = idx & 7, n = (idx >> 3) & 63, hh = (idx >> 9) & 3, p = idx >> 11;
    int c0 = ch2 * 2;
    float vv0 = sout[(p * 64 + c0 * 4 + hh) * 65 + n];
    float vv1 = sout[(p * 64 + (c0 + 1) * 4 + hh) * 65 + n];
    __half h0 = __float2half_rn(vv0), h1 = __float2half_rn(vv1);
    __half2 hi = __halves2half2(h0, h1);
    __half2 lo = __floats2half2_rn(vv0 - __half2float(h0), vv1 - __half2float(h1));
    int qi = (wb * 4 + hh) * 1024 + n * 16 + c0;
    if (p == 0) {
      *(__half2*)&g_qh[qi] = hi;
      *(__half2*)&g_ql[qi] = lo;
    } else {
      *(__half2*)&g_kh[qi] = hi;
      *(__half2*)&g_kl[qi] = lo;
    }
  }
  // v: fp16 transposed [hh][ch][n], half2-vectorized (key pairs)
  for (int idx = t; idx < 2048; idx += 256) {
    int n2 = idx & 31, co = idx >> 5;
    int hh = co & 3, ch = co >> 2;
    float vv0 = sout[(128 + co) * 65 + 2 * n2];
    float vv1 = sout[(128 + co) * 65 + 2 * n2 + 1];
    *(__half2*)&g_vt[(wb * 4 + hh) * 1024 + ch * 64 + 2 * n2] = __floats2half2_rn(vv0, vv1);
  }
}

// ---------------- K234: fused 3-exposure attention + GEGLU + conv1x1 + residual ----
// dyn smem u32[12800]: sgin[64][100] @0 | sya[64][100] @6400; sres f32 aliases all.
__device__ __forceinline__ ull maskw(int row, int wh, int ww) {
  ull m = 0ULL;
  if (wh == 31) m |= ((row >> 3) < 4) ? 0xFFFFFFFF00000000ULL : 0x00000000FFFFFFFFULL;
  if (ww == 31) m |= ((row & 7) < 4) ? 0xF0F0F0F0F0F0F0F0ULL : 0x0F0F0F0F0F0F0F0FULL;
  return m;
}

__global__ void __launch_bounds__(256, 2)
k234_fused(const float* __restrict__ b11, const float* __restrict__ b12,
           const float* __restrict__ b2, const float* __restrict__ x) {
  extern __shared__ unsigned smu[];
  unsigned* sgin = smu;          // [64][100]
  unsigned* sya = smu + 6400;    // [64][100] conv A-tile
  float* sres = (float*)smu;     // aliases everything after conv MMA
  __shared__ unsigned stu[64 * 36];
  int w = blockIdx.x;
  int wh = w >> 5, ww = w & 31;
  const int ekvA_of[3] = {1, 0, 1};
  const int ekvB_of[3] = {2, 2, 0};
  int t = threadIdx.x;
  int wa = t >> 5, lane = t & 31;
  int rq = lane >> 2, acol = lane & 3;
  int slot = wa >> 2, hh = wa & 3;
  for (int e = 0; e < 3; e++) {
    int qb = (e * 1024 + w) * 4096;
    // --- phase1: merged-q copy + attention (both write disjoint sgin regions) ---
    for (int idx = t; idx < 1024; idx += 256) {
      int n = idx >> 4, pr = idx & 15;
      int hh2 = pr >> 2, c2 = (pr & 3) * 4;
      uint2 qv = *(const uint2*)&g_qh[qb + hh2 * 1024 + n * 16 + c2];
      sgin[n * 100 + 64 + pr * 2] = qv.x;
      sgin[n * 100 + 64 + pr * 2 + 1] = qv.y;
    }
    {
      int ekv = slot ? ekvB_of[e] : ekvA_of[e];
      int kb = ((ekv * 1024 + w) * 4 + hh) * 1024;
      int qhb = qb + hh * 1024;
      unsigned Kfh[8][2], Kfl[8][2];
#pragma unroll
      for (int nt = 0; nt < 8; nt++) {
        int row = nt * 8 + rq;
        Kfh[nt][0] = *(const unsigned*)&g_kh[kb + row * 16 + 2 * acol];
        Kfh[nt][1] = *(const unsigned*)&g_kh[kb + row * 16 + 8 + 2 * acol];
        Kfl[nt][0] = *(const unsigned*)&g_kl[kb + row * 16 + 2 * acol];
        Kfl[nt][1] = *(const unsigned*)&g_kl[kb + row * 16 + 8 + 2 * acol];
      }
      unsigned Vf[4][2][2];
#pragma unroll
      for (int kit = 0; kit < 4; kit++)
#pragma unroll
        for (int n2 = 0; n2 < 2; n2++) {
          Vf[kit][n2][0] = *(const unsigned*)&g_vt[kb + (n2 * 8 + rq) * 64 + (kit * 8 + acol) * 2];
          Vf[kit][n2][1] = *(const unsigned*)&g_vt[kb + (n2 * 8 + rq) * 64 + (kit * 8 + 4 + acol) * 2];
        }
#pragma unroll
      for (int mt = 0; mt < 4; mt++) {
        int r0 = mt * 16 + rq;
        unsigned Ah[4], Al[4];
        Ah[0] = *(const unsigned*)&g_qh[qhb + r0 * 16 + 2 * acol];
        Ah[1] = *(const unsigned*)&g_qh[qhb + (r0 + 8) * 16 + 2 * acol];
        Ah[2] = *(const unsigned*)&g_qh[qhb + r0 * 16 + 8 + 2 * acol];
        Ah[3] = *(const unsigned*)&g_qh[qhb + (r0 + 8) * 16 + 8 + 2 * acol];
        Al[0] = *(const unsigned*)&g_ql[qhb + r0 * 16 + 2 * acol];
        Al[1] = *(const unsigned*)&g_ql[qhb + (r0 + 8) * 16 + 2 * acol];
        Al[2] = *(const unsigned*)&g_ql[qhb + r0 * 16 + 8 + 2 * acol];
        Al[3] = *(const unsigned*)&g_ql[qhb + (r0 + 8) * 16 + 8 + 2 * acol];
        float sc[8][4];
#pragma unroll
        for (int nt = 0; nt < 8; nt++) {
#pragma unroll
          for (int r = 0; r < 4; r++) sc[nt][r] = 0.f;
          mma_f16(sc[nt], Ah, Kfh[nt][0], Kfh[nt][1]);
          mma_f16(sc[nt], Ah, Kfl[nt][0], Kfl[nt][1]);
          mma_f16(sc[nt], Al, Kfh[nt][0], Kfh[nt][1]);
        }
        ull m0 = maskw(r0, wh, ww);
        ull m1 = maskw(r0 + 8, wh, ww);
        float sum0 = 0.f, sum1 = 0.f;
        unsigned Pf[4][4];
#pragma unroll
        for (int nt = 0; nt < 8; nt++) {
          int c0 = nt * 8 + 2 * acol;
          float p0 = ((m0 >> c0) & 1) ? 0.f : __expf(sc[nt][0] * 0.125f);
          float p1 = ((m0 >> (c0 + 1)) & 1) ? 0.f : __expf(sc[nt][1] * 0.125f);
          float p2 = ((m1 >> c0) & 1) ? 0.f : __expf(sc[nt][2] * 0.125f);
          float p3 = ((m1 >> (c0 + 1)) & 1) ? 0.f : __expf(sc[nt][3] * 0.125f);
          sum0 += p0 + p1;
          sum1 += p2 + p3;
          Pf[nt >> 1][(nt & 1) ? 2 : 0] = h2pk(p0, p1);
          Pf[nt >> 1][(nt & 1) ? 3 : 1] = h2pk(p2, p3);
        }
        sum0 += __shfl_xor_sync(0xFFFFFFFFu, sum0, 1);
        sum0 += __shfl_xor_sync(0xFFFFFFFFu, sum0, 2);
        sum1 += __shfl_xor_sync(0xFFFFFFFFu, sum1, 1);
        sum1 += __shfl_xor_sync(0xFFFFFFFFu, sum1, 2);
        float inv0 = 1.f / sum0, inv1 = 1.f / sum1;
        float oc[2][4];
#pragma unroll
        for (int n2 = 0; n2 < 2; n2++)
#pragma unroll
          for (int r = 0; r < 4; r++) oc[n2][r] = 0.f;
#pragma unroll
        for (int kit = 0; kit < 4; kit++)
#pragma unroll
          for (int n2 = 0; n2 < 2; n2++)
            mma_f16(oc[n2], Pf[kit], Vf[kit][n2][0], Vf[kit][n2][1]);
#pragma unroll
        for (int n2 = 0; n2 < 2; n2++) {
          int fb = slot * 32 + hh * 8 + n2 * 4 + acol;
          sgin[r0 * 100 + fb] = h2pk(oc[n2][0] * inv0, oc[n2][1] * inv0);
          sgin[(r0 + 8) * 100 + fb] = h2pk(oc[n2][2] * inv1, oc[n2][3] * inv1);
        }
      }
    }
    __syncthreads();
    // ---- GEGLU GEMM1 ----
    float a1[4][4], g1[4][4];
    {
      int o = wa * 8 + 2 * acol;
      float ba0 = b11[e * 64 + o], ba1 = b11[e * 64 + o + 1];
      float bg0 = b12[e * 64 + o], bg1 = b12[e * 64 + o + 1];
#pragma unroll
      for (int mt = 0; mt < 4; mt++) {
        a1[mt][0] = ba0; a1[mt][1] = ba1; a1[mt][2] = ba0; a1[mt][3] = ba1;
        g1[mt][0] = bg0; g1[mt][1] = bg1; g1[mt][2] = bg0; g1[mt][3] = bg1;
      }
    }
    const ull* W11 = g_wp11 + e * 3072 + wa * 12 * 32;
    const ull* W12 = g_wp12 + e * 3072 + wa * 12 * 32;
    for (int kit = 0; kit < 12; kit++) {
      unsigned A[4][4];
#pragma unroll
      for (int mt = 0; mt < 4; mt++) {
        int r = mt * 16 + rq;
        A[mt][0] = sgin[r * 100 + kit * 8 + acol];
        A[mt][1] = sgin[(r + 8) * 100 + kit * 8 + acol];
        A[mt][2] = sgin[r * 100 + kit * 8 + acol + 4];
        A[mt][3] = sgin[(r + 8) * 100 + kit * 8 + acol + 4];
      }
      ull wv1 = W11[kit * 32 + lane];
      ull wv2 = W12[kit * 32 + lane];
#pragma unroll
      for (int mt = 0; mt < 4; mt++) {
        mma_f16(a1[mt], A[mt], (unsigned)wv1, (unsigned)(wv1 >> 32));
        mma_f16(g1[mt], A[mt], (unsigned)wv2, (unsigned)(wv2 >> 32));
      }
    }
#pragma unroll
    for (int mt = 0; mt < 4; mt++) {
      int r0 = mt * 16 + rq;
      stu[r0 * 36 + wa * 4 + acol] = h2pk(gelu_exact(a1[mt][0]) * g1[mt][0],
                                          gelu_exact(a1[mt][1]) * g1[mt][1]);
      stu[(r0 + 8) * 36 + wa * 4 + acol] = h2pk(gelu_exact(a1[mt][2]) * g1[mt][2],
                                                gelu_exact(a1[mt][3]) * g1[mt][3]);
    }
    __syncthreads();
    // ---- GEGLU GEMM2 -> write y directly into conv A-tile (sya) ----
    float y2[4][4];
    {
      int o = wa * 8 + 2 * acol;
      float b0 = b2[e * 64 + o], b1v = b2[e * 64 + o + 1];
#pragma unroll
      for (int mt = 0; mt < 4; mt++) {
        y2[mt][0] = b0; y2[mt][1] = b1v; y2[mt][2] = b0; y2[mt][3] = b1v;
      }
    }
    const ull* W2 = g_wp2 + e * 1024 + wa * 4 * 32;
    for (int kit = 0; kit < 4; kit++) {
      unsigned A[4][4];
#pragma unroll
      for (int mt = 0; mt < 4; mt++) {
        int r = mt * 16 + rq;
        A[mt][0] = stu[r * 36 + kit * 8 + acol];
        A[mt][1] = stu[(r + 8) * 36 + kit * 8 + acol];
        A[mt][2] = stu[r * 36 + kit * 8 + acol + 4];
        A[mt][3] = stu[(r + 8) * 36 + kit * 8 + acol + 4];
      }
      ull wv = W2[kit * 32 + lane];
#pragma unroll
      for (int mt = 0; mt < 4; mt++)
        mma_f16(y2[mt], A[mt], (unsigned)wv, (unsigned)(wv >> 32));
    }
    int kkb = e * 32 + wa * 4 + acol;
#pragma unroll
    for (int mt = 0; mt < 4; mt++) {
      int r0 = mt * 16 + rq;
      sya[r0 * 100 + kkb] = h2pk(y2[mt][0], y2[mt][1]);
      sya[(r0 + 8) * 100 + kkb] = h2pk(y2[mt][2], y2[mt][3]);
    }
    __syncthreads();
  }
  // ---- conv1x1 (192x192) over the assembled y tile ----
  float acc[3][4][4];
#pragma unroll
  for (int j = 0; j < 3; j++)
#pragma unroll
    for (int mt = 0; mt < 4; mt++)
#pragma unroll
      for (int r = 0; r < 4; r++) acc[j][mt][r] = 0.f;
  for (int kit = 0; kit < 12; kit++) {
    unsigned A[4][4];
#pragma unroll
    for (int mt = 0; mt < 4; mt++) {
      int r = mt * 16 + rq;
      A[mt][0] = sya[r * 100 + kit * 8 + acol];
      A[mt][1] = sya[(r + 8) * 100 + kit * 8 + acol];
      A[mt][2] = sya[r * 100 + kit * 8 + acol + 4];
      A[mt][3] = sya[(r + 8) * 100 + kit * 8 + acol + 4];
    }
#pragma unroll
    for (int j = 0; j < 3; j++) {
      ull wv = g_wp192[((wa * 3 + j) * 12 + kit) * 32 + lane];
#pragma unroll
      for (int mt = 0; mt < 4; mt++)
        mma_f16(acc[j][mt], A[mt], (unsigned)wv, (unsigned)(wv >> 32));
    }
  }
  __syncthreads();   // sya fully consumed; sres may alias it now
  int ccol0 = 2 * acol;
#pragma unroll
  for (int j = 0; j < 3; j++) {
    int oc = (wa * 3 + j) * 8 + ccol0;
#pragma unroll
    for (int mt = 0; mt < 4; mt++) {
      int r0 = mt * 16 + rq;
      sres[oc * 65 + r0] = acc[j][mt][0];
      sres[(oc + 1) * 65 + r0] = acc[j][mt][1];
      sres[oc * 65 + r0 + 8] = acc[j][mt][2];
      sres[(oc + 1) * 65 + r0 + 8] = acc[j][mt][3];
    }
  }
  __syncthreads();
  for (int idx = t; idx < 12288; idx += 256) {
    int n = idx & 63, oc = idx >> 6;
    int i = n >> 3, j = n & 7;
    int hp = (wh * 8 + i + 4) & 255;
    int wp = (ww * 8 + j + 4) & 255;
    int gi = oc * 65536 + hp * 256 + wp;
    g_xres[gi] = sres[oc * 65 + n] + x[gi];
  }
}

// ---------------- K5: LN2 + ff_in (192->768) fp16 MMA ------------------------------
// dyn f32[14848]: sxn [64][196] @0 (dies) | sxh u32 [64][100] @0 (in-place) | sfl @6400
__global__ void k5_ln_ffin(const float* __restrict__ ln2w, const float* __restrict__ ln2b) {
  extern __shared__ float sm5[];
  float* sxn = sm5;
  unsigned* sxh = (unsigned*)sm5;
  float* sfl = sm5 + 6400;
  __shared__ float red[256], red2[256], smean[64], srstd[64];
  int blk = blockIdx.x;
  int h = blk >> 2;
  int w0 = (blk & 3) * 64;
  int pix0 = h * 256 + w0;
  int t = threadIdx.x;
  for (int idx = t; idx < 12288; idx += 256) {
    int c = idx >> 6, p = idx & 63;
    sxn[p * 196 + c] = g_xres[c * 65536 + pix0 + p];
  }
  __syncthreads();
  {
    int p = t & 63, g = t >> 6;
    float s = 0.f, s2v = 0.f;
    for (int c = g; c < 192; c += 4) { float v = sxn[p * 196 + c]; s += v; s2v += v * v; }
    red[t] = s;
    red2[t] = s2v;
  }
  __syncthreads();
  if (t < 64) {
    float s = red[t] + red[64 + t] + red[128 + t] + red[192 + t];
    float s2v = red2[t] + red2[64 + t] + red2[128 + t] + red2[192 + t];
    float m = s * (1.f / 192.f);
    float var = s2v * (1.f / 192.f) - m * m;
    smean[t] = m;
    srstd[t] = rsqrtf(var + 1e-5f);
  }
  __syncthreads();
  // in-place f32 -> fp16 conversion via register staging (sxh aliases sxn)
  unsigned tmp[24];
#pragma unroll
  for (int k = 0; k < 24; k++) {
    int idx = t + k * 256;
    int p = idx / 96, kk = idx - p * 96;
    int c = kk * 2;
    float v0 = (sxn[p * 196 + c] - smean[p]) * srstd[p] * ln2w[c] + ln2b[c];
    float v1 = (sxn[p * 196 + c + 1] - smean[p]) * srstd[p] * ln2w[c + 1] + ln2b[c + 1];
    tmp[k] = h2pk(v0, v1);
  }
  __syncthreads();
#pragma unroll
  for (int k = 0; k < 24; k++) {
    int idx = t + k * 256;
    int p = idx / 96, kk = idx - p * 96;
    sxh[p * 100 + kk] = tmp[k];
  }
  __syncthreads();
  int wa = t >> 5, lane = t & 31;
  int rq = lane >> 2, acol = lane & 3, ccol0 = 2 * acol;
  for (int ch = 0; ch < 6; ch++) {
    float acc[2][4][4];
#pragma unroll
    for (int j = 0; j < 2; j++)
#pragma unroll
      for (int mt = 0; mt < 4; mt++)
#pragma unroll
        for (int r = 0; r < 4; r++) acc[j][mt][r] = 0.f;
    for (int kit = 0; kit < 12; kit++) {
      unsigned A[4][4];
#pragma unroll
      for (int mt = 0; mt < 4; mt++) {
        int r = mt * 16 + rq;
        A[mt][0] = sxh[r * 100 + kit * 8 + acol];
        A[mt][1] = sxh[(r + 8) * 100 + kit * 8 + acol];
        A[mt][2] = sxh[r * 100 + kit * 8 + acol + 4];
        A[mt][3] = sxh[(r + 8) * 100 + kit * 8 + acol + 4];
      }
#pragma unroll
      for (int j = 0; j < 2; j++) {
        int nt = wa * 12 + ch * 2 + j;
        ull wv = g_wp_in[(nt * 12 + kit) * 32 + lane];
#pragma unroll
        for (int mt = 0; mt < 4; mt++)
          mma_f16(acc[j][mt], A[mt], (unsigned)wv, (unsigned)(wv >> 32));
      }
    }
#pragma unroll
    for (int j = 0; j < 2; j++) {
      int lc = (wa * 2 + j) * 8 + ccol0;
#pragma unroll
      for (int mt = 0; mt < 4; mt++) {
        int r0 = mt * 16 + rq;
        sfl[lc * 66 + r0] = acc[j][mt][0];
        sfl[(lc + 1) * 66 + r0] = acc[j][mt][1];
        sfl[lc * 66 + r0 + 8] = acc[j][mt][2];
        sfl[(lc + 1) * 66 + r0 + 8] = acc[j][mt][3];
      }
    }
    __syncthreads();
    for (int idx = t; idx < 4096; idx += 256) {
      int lc = idx >> 5, p2 = (idx & 31) * 2;
      int o = ((lc >> 4) * 12 + ch * 2 + ((lc >> 3) & 1)) * 8 + (lc & 7);
      *(__half2*)&g_hbh[o * 65536 + pix0 + p2] =
          __floats2half2_rn(sfl[lc * 66 + p2], sfl[lc * 66 + p2 + 1]);
    }
    __syncthreads();
  }
}

// ---------------- K6: depthwise 3x3 + gelu(g1)*g2, 16 rows/block, half2 ------------
__global__ void k6_dw(const float* __restrict__ dw) {
  __shared__ float s0[18][264];
  __shared__ float s1[18][264];
  int h0 = blockIdx.x * 16;
  int c = blockIdx.y;
  int t = threadIdx.x;
  const __half* p0 = g_hbh + c * 65536;
  const __half* p1 = g_hbh + (c + 384) * 65536;
  for (int idx = t; idx < 18 * 128; idx += 256) {
    int r = idx >> 7, cc = idx & 127;
    int hh = h0 - 1 + r;
    float2 v0 = make_float2(0.f, 0.f), v1 = make_float2(0.f, 0.f);
    if (hh >= 0 && hh < 256) {
      v0 = __half22float2(*(const __half2*)&p0[hh * 256 + cc * 2]);
      v1 = __half22float2(*(const __half2*)&p1[hh * 256 + cc * 2]);
    }
    s0[r][1 + 2 * cc] = v0.x;
    s0[r][2 + 2 * cc] = v0.y;
    s1[r][1 + 2 * cc] = v1.x;
    s1[r][2 + 2 * cc] = v1.y;
  }
  if (t < 18) { s0[t][0] = 0.f; s0[t][257] = 0.f; s1[t][0] = 0.f; s1[t][257] = 0.f; }
  float f0r[9], f1r[9];
#pragma unroll
  for (int k = 0; k < 9; k++) { f0r[k] = dw[c * 9 + k]; f1r[k] = dw[(c + 384) * 9 + k]; }
  __syncthreads();
  int cp = (t & 127) * 2;
  int rg = t >> 7;
#pragma unroll
  for (int r = 0; r < 8; r++) {
    int row = rg * 8 + r;
    float a0 = 0.f, b0 = 0.f, a1 = 0.f, b1 = 0.f;
#pragma unroll
    for (int dh = 0; dh < 3; dh++) {
#pragma unroll
      for (int dwi = 0; dwi < 3; dwi++) {
        float w = f0r[dh * 3 + dwi];
        float wv = f1r[dh * 3 + dwi];
        a0 += s0[row + dh][cp + dwi] * w;
        a1 += s0[row + dh][cp + 1 + dwi] * w;
        b0 += s1[row + dh][cp + dwi] * wv;
        b1 += s1[row + dh][cp + 1 + dwi] * wv;
      }
    }
    float o0 = gelu_exact(a0) * b0;
    float o1 = gelu_exact(a1) * b1;
    *(__half2*)&g_gbh[c * 65536 + (h0 + row) * 256 + cp] = __floats2half2_rn(o0, o1);
  }
}

// ---------------- K7: ff_out (384->192) + residual, fp16 MMA -----------------------
__global__ void k7_ffout(float* __restrict__ out) {
  extern __shared__ unsigned sA[];
  __shared__ float sfl2[192 * 34];
  int blk = blockIdx.x;
  int h = blk >> 3;
  int w0 = (blk & 7) * 32;
  int pix0 = h * 256 + w0;
  int t = threadIdx.x;
  for (int idx = t; idx < 6144; idx += 256) {
    int p = idx & 31, kk = idx >> 5;
    int c = kk * 2;
    __half h0 = g_gbh[c * 65536 + pix0 + p];
    __half h1 = g_gbh[(c + 1) * 65536 + pix0 + p];
    __half2 hv = __halves2half2(h0, h1);
    sA[p * 196 + kk] = *(unsigned*)&hv;
  }
  __syncthreads();
  int wa = t >> 5, lane = t & 31;
  int rq = lane >> 2, acol = lane & 3, ccol0 = 2 * acol;
  float acc[3][2][4];
#pragma unroll
  for (int j = 0; j < 3; j++)
#pragma unroll
    for (int mt = 0; mt < 2; mt++)
#pragma unroll
      for (int r = 0; r < 4; r++) acc[j][mt][r] = 0.f;
  for (int kit = 0; kit < 24; kit++) {
    unsigned A[2][4];
#pragma unroll
    for (int mt = 0; mt < 2; mt++) {
      int r = mt * 16 + rq;
      A[mt][0] = sA[r * 196 + kit * 8 + acol];
      A[mt][1] = sA[(r + 8) * 196 + kit * 8 + acol];
      A[mt][2] = sA[r * 196 + kit * 8 + acol + 4];
      A[mt][3] = sA[(r + 8) * 196 + kit * 8 + acol + 4];
    }
#pragma unroll
    for (int j = 0; j < 3; j++) {
      ull wv = g_wp_out[((wa * 3 + j) * 24 + kit) * 32 + lane];
#pragma unroll
      for (int mt = 0; mt < 2; mt++)
        mma_f16(acc[j][mt], A[mt], (unsigned)wv, (unsigned)(wv >> 32));
    }
  }
#pragma unroll
  for (int j = 0; j < 3; j++) {
    int oc = (wa * 3 + j) * 8 + ccol0;
#pragma unroll
    for (int mt = 0; mt < 2; mt++) {
      int r0 = mt * 16 + rq;
      sfl2[oc * 34 + r0] = acc[j][mt][0];
      sfl2[(oc + 1) * 34 + r0] = acc[j][mt][1];
      sfl2[oc * 34 + r0 + 8] = acc[j][mt][2];
      sfl2[(oc + 1) * 34 + r0 + 8] = acc[j][mt][3];
    }
  }
  __syncthreads();
  for (int idx = t; idx < 6144; idx += 256) {
    int oc = idx >> 5, p = idx & 31;
    int gi = oc * 65536 + pix0 + p;
    out[gi] = g_xres[gi] + sfl2[oc * 34 + p];
  }
}

// ---------------- host launcher ----------------------------------------------------
extern "C" void kernel_launch(void* const* d_in, const int* in_sizes, int n_in,
                              void* d_out, int out_size) {
  const float* x    = (const float*)d_in[0];
  const float* ln1w = (const float*)d_in[1];
  const float* ln1b = (const float*)d_in[2];
  const float* ln2w = (const float*)d_in[3];
  const float* ln2b = (const float*)d_in[4];
  const float* wqkv = (const float*)d_in[5];
  const float* w11  = (const float*)d_in[6];
  const float* b11  = (const float*)d_in[7];
  const float* w12  = (const float*)d_in[8];
  const float* b12  = (const float*)d_in[9];
  const float* w2   = (const float*)d_in[10];
  const float* b2   = (const float*)d_in[11];
  const float* c11  = (const float*)d_in[12];
  const float* ffin = (const float*)d_in[13];
  const float* ffdw = (const float*)d_in[14];
  const float* ffou = (const float*)d_in[15];
  float* out = (float*)d_out;

  const int smem1 = 192 * 65 * 4;                 // 49920
  const int smem234 = 12800 * 4;                  // 51200
  const int smem5 = 14848 * 4;                    // 59392
  const int smem7 = 32 * 196 * 4;                 // 25088
  cudaFuncSetAttribute(k1_qkv, cudaFuncAttributeMaxDynamicSharedMemorySize, smem1);
  cudaFuncSetAttribute(k234_fused, cudaFuncAttributeMaxDynamicSharedMemorySize, smem234);
  cudaFuncSetAttribute(k5_ln_ffin, cudaFuncAttributeMaxDynamicSharedMemorySize, smem5);
  cudaFuncSetAttribute(k7_ffout, cudaFuncAttributeMaxDynamicSharedMemorySize, smem7);

  kpos<<<1, 64>>>();
  kpack<<<144, 256>>>(c11, ffin, ffou, w11, w12, w2, wqkv);
  k1_qkv<<<3072, 256, smem1>>>(x, ln1w, ln1b);
  k234_fused<<<1024, 256, smem234>>>(b11, b12, b2, x);
  k5_ln_ffin<<<1024, 256, smem5>>>(ln2w, ln2b);
  {
    dim3 g6(16, 384);
    k6_dw<<<g6, 256>>>(ffdw);
  }
  k7_ffout<<<2048, 256, smem7>>>(out);
}

// round 15
// speedup vs baseline: 1.0142x; 1.0142x over previous
#include <cuda_runtime.h>
#include <cuda_fp16.h>
#include <math.h>

typedef unsigned long long ull;

// ---------------- fp16 MMA helpers -------------------------------------------------
__device__ __forceinline__ unsigned h2pk(float a, float b) {
  __half2 h = __floats2half2_rn(a, b);
  return *(unsigned*)&h;
}
__device__ __forceinline__ void mma_f16(float* c, const unsigned* a, unsigned b0, unsigned b1) {
  asm volatile(
      "mma.sync.aligned.m16n8k16.row.col.f32.f16.f16.f32 "
      "{%0,%1,%2,%3},{%4,%5,%6,%7},{%8,%9},{%0,%1,%2,%3};"
      : "+f"(c[0]), "+f"(c[1]), "+f"(c[2]), "+f"(c[3])
      : "r"(a[0]), "r"(a[1]), "r"(a[2]), "r"(a[3]), "r"(b0), "r"(b1));
}
__device__ __forceinline__ float gelu_exact(float a) {
  return 0.5f * a * (1.f + erff(a * 0.70710678118654752f));
}

// ---------------- static device scratch --------------------------------------------
__device__ float g_pos[64 * 64];
__device__ __half g_qh[3 * 1024 * 4096];
__device__ __half g_ql[3 * 1024 * 4096];
__device__ __half g_kh[3 * 1024 * 4096];
__device__ __half g_kl[3 * 1024 * 4096];
__device__ __half g_vt[3 * 1024 * 4096];
__device__ float g_xres[192 * 65536];
__device__ __half g_hbh[768 * 65536];
__device__ __half g_gbh[384 * 65536];
// packed fp16 weight fragments: [ntile][kit16][lane] -> (b0 | b1<<32)
__device__ ull g_wp_in[96 * 12 * 32];     // ff_in  (K=192, N=768)
__device__ ull g_wp_out[24 * 24 * 32];    // ff_out (K=384, N=192)
__device__ ull g_wp11[3 * 8 * 12 * 32];   // me_w11 (K=192, N=64)
__device__ ull g_wp12[3 * 8 * 12 * 32];   // me_w12
__device__ ull g_wp2[3 * 8 * 4 * 32];     // me_w2  (K=64,  N=64)
__device__ ull g_wpqkv[24 * 4 * 32];      // w_qkv  (K=64,  N=192)
__device__ ull g_wp192[24 * 12 * 32];     // conv11 (K=192, N=192)

// ---------------- K0a: sine positional encoding ------------------------------------
__global__ void kpos() {
  int n = threadIdx.x;
  int i = n >> 3, j = n & 7;
  double scale = 6.283185307179586476925286766559;
  double yv = (double)(i + 1) / (8.0 + 1e-6) * scale;
  double xv = (double)(j + 1) / (8.0 + 1e-6) * scale;
  for (int c = 0; c < 64; c++) {
    double base = (c < 32) ? yv : xv;
    int k = (c < 32) ? c : (c - 32);
    double dt = pow(10000.0, (double)(k >> 1) / 16.0);
    double v = base / dt;
    g_pos[n * 64 + c] = (float)(((k & 1) == 0) ? sin(v) : cos(v));
  }
}

// ---------------- K0b: fp16 fragment packing ---------------------------------------
__global__ void kpack(const float* __restrict__ c11, const float* __restrict__ ffin,
                      const float* __restrict__ ffout, const float* __restrict__ w11,
                      const float* __restrict__ w12, const float* __restrict__ w2,
                      const float* __restrict__ wqkv) {
  int idx = blockIdx.x * 256 + threadIdx.x;
  int lane = idx & 31;
  if (idx < 36864) {  // wp_in [96][12][32], src [o=768][k=192]
    int kit = (idx >> 5) % 12, nt = idx / 384;
    int o = nt * 8 + (lane >> 2), k0 = kit * 16 + (lane & 3) * 2;
    unsigned b0 = h2pk(ffin[o * 192 + k0], ffin[o * 192 + k0 + 1]);
    unsigned b1 = h2pk(ffin[o * 192 + k0 + 8], ffin[o * 192 + k0 + 9]);
    g_wp_in[idx] = (ull)b0 | ((ull)b1 << 32);
  }
  if (idx < 18432) {  // wp_out [24][24][32], src [o=192][k=384]
    int kit = (idx >> 5) % 24, nt = idx / 768;
    int o = nt * 8 + (lane >> 2), k0 = kit * 16 + (lane & 3) * 2;
    unsigned b0 = h2pk(ffout[o * 384 + k0], ffout[o * 384 + k0 + 1]);
    unsigned b1 = h2pk(ffout[o * 384 + k0 + 8], ffout[o * 384 + k0 + 9]);
    g_wp_out[idx] = (ull)b0 | ((ull)b1 << 32);
  }
  if (idx < 9216) {  // wp11/wp12 [3][8][12][32], src [e][k=192][f=64]
    int e = idx / 3072, r = idx % 3072;
    int kit = (r >> 5) % 12, nt = r / 384;
    int f = nt * 8 + (lane >> 2), k0 = kit * 16 + (lane & 3) * 2;
    const float* Wa = w11 + e * 12288;
    const float* Wb = w12 + e * 12288;
    unsigned a0 = h2pk(Wa[k0 * 64 + f], Wa[(k0 + 1) * 64 + f]);
    unsigned a1 = h2pk(Wa[(k0 + 8) * 64 + f], Wa[(k0 + 9) * 64 + f]);
    g_wp11[idx] = (ull)a0 | ((ull)a1 << 32);
    unsigned c0 = h2pk(Wb[k0 * 64 + f], Wb[(k0 + 1) * 64 + f]);
    unsigned c1 = h2pk(Wb[(k0 + 8) * 64 + f], Wb[(k0 + 9) * 64 + f]);
    g_wp12[idx] = (ull)c0 | ((ull)c1 << 32);
  }
  if (idx < 3072) {  // wp2 [3][8][4][32], src [e][k=64][f=64]
    int e = idx / 1024, r = idx % 1024;
    int kit = (r >> 5) % 4, nt = r / 128;
    int f = nt * 8 + (lane >> 2), k0 = kit * 16 + (lane & 3) * 2;
    const float* Wa = w2 + e * 4096;
    unsigned b0 = h2pk(Wa[k0 * 64 + f], Wa[(k0 + 1) * 64 + f]);
    unsigned b1 = h2pk(Wa[(k0 + 8) * 64 + f], Wa[(k0 + 9) * 64 + f]);
    g_wp2[idx] = (ull)b0 | ((ull)b1 << 32);
  }
  if (idx < 3072) {  // wpqkv [24][4][32], src [k=64][n=192]
    int kit = (idx >> 5) % 4, nt = idx / 128;
    int n = nt * 8 + (lane >> 2), k0 = kit * 16 + (lane & 3) * 2;
    unsigned b0 = h2pk(wqkv[k0 * 192 + n], wqkv[(k0 + 1) * 192 + n]);
    unsigned b1 = h2pk(wqkv[(k0 + 8) * 192 + n], wqkv[(k0 + 9) * 192 + n]);
    g_wpqkv[idx] = (ull)b0 | ((ull)b1 << 32);
  }
  if (idx < 9216) {  // wp192 [24][12][32], src [o=192][k=192]
    int kit = (idx >> 5) % 12, nt = idx / 384;
    int o = nt * 8 + (lane >> 2), k0 = kit * 16 + (lane & 3) * 2;
    unsigned b0 = h2pk(c11[o * 192 + k0], c11[o * 192 + k0 + 1]);
    unsigned b1 = h2pk(c11[o * 192 + k0 + 8], c11[o * 192 + k0 + 9]);
    g_wp192[idx] = (ull)b0 | ((ull)b1 << 32);
  }
}

// ---------------- K1: shift+window + LN1 + pos + QKV GEMM (fp16 MMA) ---------------
__global__ void k1_qkv(const float* __restrict__ x, const float* __restrict__ ln1w,
                       const float* __restrict__ ln1b) {
  extern __shared__ float sm1[];
  float* sx = sm1;
  unsigned* snT = (unsigned*)(sm1 + 4160);
  float* sout = sm1;
  __shared__ float smean[64], srstd[64];
  int blk = blockIdx.x;
  int e = blk >> 10, wwin = blk & 1023;
  int wh = wwin >> 5, ww = wwin & 31;
  int t = threadIdx.x;
  for (int idx = t; idx < 4096; idx += 256) {
    int c = idx >> 6, n = idx & 63;
    int i = n >> 3, j = n & 7;
    int h0 = (wh * 8 + i + 4) & 255;
    int w0 = (ww * 8 + j + 4) & 255;
    sx[n * 65 + c] = x[((e * 64 + c) * 256 + h0) * 256 + w0];
  }
  __syncthreads();
  if (t < 64) {
    int n = t;
    float m = 0.f;
#pragma unroll
    for (int c = 0; c < 64; c++) m += sx[n * 65 + c];
    m *= (1.f / 64.f);
    float v = 0.f;
#pragma unroll
    for (int c = 0; c < 64; c++) { float d = sx[n * 65 + c] - m; v += d * d; }
    v *= (1.f / 64.f);
    smean[n] = m;
    srstd[n] = rsqrtf(v + 1e-5f);
  }
  __syncthreads();
  for (int idx = t; idx < 2048; idx += 256) {
    int n = idx >> 5, kk = idx & 31;
    int c = kk * 2;
    float v0 = (sx[n * 65 + c] - smean[n]) * srstd[n] * ln1w[c] + ln1b[c] + g_pos[n * 64 + c];
    float v1 = (sx[n * 65 + c + 1] - smean[n]) * srstd[n] * ln1w[c + 1] + ln1b[c + 1] + g_pos[n * 64 + c + 1];
    snT[n * 36 + kk] = h2pk(v0, v1);
  }
  __syncthreads();
  int wa = t >> 5, lane = t & 31;
  int rq = lane >> 2, acol = lane & 3, ccol0 = 2 * acol;
  float acc[3][4][4];
#pragma unroll
  for (int j = 0; j < 3; j++)
#pragma unroll
    for (int mt = 0; mt < 4; mt++)
#pragma unroll
      for (int r = 0; r < 4; r++) acc[j][mt][r] = 0.f;
  for (int kit = 0; kit < 4; kit++) {
    unsigned A[4][4];
#pragma unroll
    for (int mt = 0; mt < 4; mt++) {
      int r = mt * 16 + rq;
      A[mt][0] = snT[r * 36 + kit * 8 + acol];
      A[mt][1] = snT[(r + 8) * 36 + kit * 8 + acol];
      A[mt][2] = snT[r * 36 + kit * 8 + acol + 4];
      A[mt][3] = snT[(r + 8) * 36 + kit * 8 + acol + 4];
    }
#pragma unroll
    for (int j = 0; j < 3; j++) {
      ull wv = g_wpqkv[((wa * 3 + j) * 4 + kit) * 32 + lane];
#pragma unroll
      for (int mt = 0; mt < 4; mt++)
        mma_f16(acc[j][mt], A[mt], (unsigned)wv, (unsigned)(wv >> 32));
    }
  }
  __syncthreads();
#pragma unroll
  for (int j = 0; j < 3; j++) {
    int jc = (wa * 3 + j) * 8 + ccol0;
#pragma unroll
    for (int mt = 0; mt < 4; mt++) {
      int r0 = mt * 16 + rq;
      sout[jc * 65 + r0] = acc[j][mt][0];
      sout[(jc + 1) * 65 + r0] = acc[j][mt][1];
      sout[jc * 65 + r0 + 8] = acc[j][mt][2];
      sout[(jc + 1) * 65 + r0 + 8] = acc[j][mt][3];
    }
  }
  __syncthreads();
  long wb = (long)(e * 1024 + wwin);
  // q/k: hi/lo fp16 split, half2-vectorized (channel pairs)
  for (int idx = t; idx < 4096; idx += 256) {
    int ch2 = idx & 7, n = (idx >> 3) & 63, hh = (idx >> 9) & 3, p = idx >> 11;
    int c0 = ch2 * 2;
    float vv0 = sout[(p * 64 + c0 * 4 + hh) * 65 + n];
    float vv1 = sout[(p * 64 + (c0 + 1) * 4 + hh) * 65 + n];
    __half h0 = __float2half_rn(vv0), h1 = __float2half_rn(vv1);
    __half2 hi = __halves2half2(h0, h1);
    __half2 lo = __floats2half2_rn(vv0 - __half2float(h0), vv1 - __half2float(h1));
    long qi = (wb * 4 + hh) * 1024 + n * 16 + c0;
    if (p == 0) {
      *(__half2*)&g_qh[qi] = hi;
      *(__half2*)&g_ql[qi] = lo;
    } else {
      *(__half2*)&g_kh[qi] = hi;
      *(__half2*)&g_kl[qi] = lo;
    }
  }
  // v: fp16 transposed [hh][ch][n], half2-vectorized (key pairs)
  for (int idx = t; idx < 2048; idx += 256) {
    int n2 = idx & 31, co = idx >> 5;
    int hh = co & 3, ch = co >> 2;
    float vv0 = sout[(128 + co) * 65 + 2 * n2];
    float vv1 = sout[(128 + co) * 65 + 2 * n2 + 1];
    *(__half2*)&g_vt[(wb * 4 + hh) * 1024 + ch * 64 + 2 * n2] = __floats2half2_rn(vv0, vv1);
  }
}

// ---------------- K234: fused 3-exposure attention + GEGLU + conv1x1 + residual ----
// dyn smem u32[12800]: sgin[64][100] @0 | sya[64][100] @6400; sres f32 aliases all.
__device__ __forceinline__ ull maskw(int row, int wh, int ww) {
  ull m = 0ULL;
  if (wh == 31) m |= ((row >> 3) < 4) ? 0xFFFFFFFF00000000ULL : 0x00000000FFFFFFFFULL;
  if (ww == 31) m |= ((row & 7) < 4) ? 0xF0F0F0F0F0F0F0F0ULL : 0x0F0F0F0F0F0F0F0FULL;
  return m;
}

__global__ void __launch_bounds__(256, 2)
k234_fused(const float* __restrict__ b11, const float* __restrict__ b12,
           const float* __restrict__ b2, const float* __restrict__ x) {
  extern __shared__ unsigned smu[];
  unsigned* sgin = smu;          // [64][100]
  unsigned* sya = smu + 6400;    // [64][100] conv A-tile
  float* sres = (float*)smu;     // aliases everything after conv MMA
  __shared__ unsigned stu[64 * 36];
  int w = blockIdx.x;
  int wh = w >> 5, ww = w & 31;
  const int ekvA_of[3] = {1, 0, 1};
  const int ekvB_of[3] = {2, 2, 0};
  int t = threadIdx.x;
  int wa = t >> 5, lane = t & 31;
  int rq = lane >> 2, acol = lane & 3;
  int slot = wa >> 2, hh = wa & 3;
  for (int e = 0; e < 3; e++) {
    long qb = (long)(e * 1024 + w) * 4096;
    // --- phase1: merged-q copy + attention (both write disjoint sgin regions) ---
    for (int idx = t; idx < 1024; idx += 256) {
      int n = idx >> 4, pr = idx & 15;
      int hh2 = pr >> 2, c2 = (pr & 3) * 4;
      uint2 qv = *(const uint2*)&g_qh[qb + hh2 * 1024 + n * 16 + c2];
      sgin[n * 100 + 64 + pr * 2] = qv.x;
      sgin[n * 100 + 64 + pr * 2 + 1] = qv.y;
    }
    {
      int ekv = slot ? ekvB_of[e] : ekvA_of[e];
      long kb = ((long)(ekv * 1024 + w) * 4 + hh) * 1024;
      long qhb = qb + hh * 1024;
      unsigned Kfh[8][2], Kfl[8][2];
#pragma unroll
      for (int nt = 0; nt < 8; nt++) {
        int row = nt * 8 + rq;
        Kfh[nt][0] = *(const unsigned*)&g_kh[kb + row * 16 + 2 * acol];
        Kfh[nt][1] = *(const unsigned*)&g_kh[kb + row * 16 + 8 + 2 * acol];
        Kfl[nt][0] = *(const unsigned*)&g_kl[kb + row * 16 + 2 * acol];
        Kfl[nt][1] = *(const unsigned*)&g_kl[kb + row * 16 + 8 + 2 * acol];
      }
      unsigned Vf[4][2][2];
#pragma unroll
      for (int kit = 0; kit < 4; kit++)
#pragma unroll
        for (int n2 = 0; n2 < 2; n2++) {
          Vf[kit][n2][0] = *(const unsigned*)&g_vt[kb + (n2 * 8 + rq) * 64 + (kit * 8 + acol) * 2];
          Vf[kit][n2][1] = *(const unsigned*)&g_vt[kb + (n2 * 8 + rq) * 64 + (kit * 8 + 4 + acol) * 2];
        }
#pragma unroll
      for (int mt = 0; mt < 4; mt++) {
        int r0 = mt * 16 + rq;
        unsigned Ah[4], Al[4];
        Ah[0] = *(const unsigned*)&g_qh[qhb + r0 * 16 + 2 * acol];
        Ah[1] = *(const unsigned*)&g_qh[qhb + (r0 + 8) * 16 + 2 * acol];
        Ah[2] = *(const unsigned*)&g_qh[qhb + r0 * 16 + 8 + 2 * acol];
        Ah[3] = *(const unsigned*)&g_qh[qhb + (r0 + 8) * 16 + 8 + 2 * acol];
        Al[0] = *(const unsigned*)&g_ql[qhb + r0 * 16 + 2 * acol];
        Al[1] = *(const unsigned*)&g_ql[qhb + (r0 + 8) * 16 + 2 * acol];
        Al[2] = *(const unsigned*)&g_ql[qhb + r0 * 16 + 8 + 2 * acol];
        Al[3] = *(const unsigned*)&g_ql[qhb + (r0 + 8) * 16 + 8 + 2 * acol];
        float sc[8][4];
#pragma unroll
        for (int nt = 0; nt < 8; nt++) {
#pragma unroll
          for (int r = 0; r < 4; r++) sc[nt][r] = 0.f;
          mma_f16(sc[nt], Ah, Kfh[nt][0], Kfh[nt][1]);
          mma_f16(sc[nt], Ah, Kfl[nt][0], Kfl[nt][1]);
          mma_f16(sc[nt], Al, Kfh[nt][0], Kfh[nt][1]);
        }
        ull m0 = maskw(r0, wh, ww);
        ull m1 = maskw(r0 + 8, wh, ww);
        float sum0 = 0.f, sum1 = 0.f;
        unsigned Pf[4][4];
#pragma unroll
        for (int nt = 0; nt < 8; nt++) {
          int c0 = nt * 8 + 2 * acol;
          float p0 = ((m0 >> c0) & 1) ? 0.f : __expf(sc[nt][0] * 0.125f);
          float p1 = ((m0 >> (c0 + 1)) & 1) ? 0.f : __expf(sc[nt][1] * 0.125f);
          float p2 = ((m1 >> c0) & 1) ? 0.f : __expf(sc[nt][2] * 0.125f);
          float p3 = ((m1 >> (c0 + 1)) & 1) ? 0.f : __expf(sc[nt][3] * 0.125f);
          sum0 += p0 + p1;
          sum1 += p2 + p3;
          Pf[nt >> 1][(nt & 1) ? 2 : 0] = h2pk(p0, p1);
          Pf[nt >> 1][(nt & 1) ? 3 : 1] = h2pk(p2, p3);
        }
        sum0 += __shfl_xor_sync(0xFFFFFFFFu, sum0, 1);
        sum0 += __shfl_xor_sync(0xFFFFFFFFu, sum0, 2);
        sum1 += __shfl_xor_sync(0xFFFFFFFFu, sum1, 1);
        sum1 += __shfl_xor_sync(0xFFFFFFFFu, sum1, 2);
        float inv0 = 1.f / sum0, inv1 = 1.f / sum1;
        float oc[2][4];
#pragma unroll
        for (int n2 = 0; n2 < 2; n2++)
#pragma unroll
          for (int r = 0; r < 4; r++) oc[n2][r] = 0.f;
#pragma unroll
        for (int kit = 0; kit < 4; kit++)
#pragma unroll
          for (int n2 = 0; n2 < 2; n2++)
            mma_f16(oc[n2], Pf[kit], Vf[kit][n2][0], Vf[kit][n2][1]);
#pragma unroll
        for (int n2 = 0; n2 < 2; n2++) {
          int fb = slot * 32 + hh * 8 + n2 * 4 + acol;
          sgin[r0 * 100 + fb] = h2pk(oc[n2][0] * inv0, oc[n2][1] * inv0);
          sgin[(r0 + 8) * 100 + fb] = h2pk(oc[n2][2] * inv1, oc[n2][3] * inv1);
        }
      }
    }
    __syncthreads();
    // ---- GEGLU GEMM1 ----
    float a1[4][4], g1[4][4];
    {
      int o = wa * 8 + 2 * acol;
      float ba0 = b11[e * 64 + o], ba1 = b11[e * 64 + o + 1];
      float bg0 = b12[e * 64 + o], bg1 = b12[e * 64 + o + 1];
#pragma unroll
      for (int mt = 0; mt < 4; mt++) {
        a1[mt][0] = ba0; a1[mt][1] = ba1; a1[mt][2] = ba0; a1[mt][3] = ba1;
        g1[mt][0] = bg0; g1[mt][1] = bg1; g1[mt][2] = bg0; g1[mt][3] = bg1;
      }
    }
    const ull* W11 = g_wp11 + e * 3072 + wa * 12 * 32;
    const ull* W12 = g_wp12 + e * 3072 + wa * 12 * 32;
    for (int kit = 0; kit < 12; kit++) {
      unsigned A[4][4];
#pragma unroll
      for (int mt = 0; mt < 4; mt++) {
        int r = mt * 16 + rq;
        A[mt][0] = sgin[r * 100 + kit * 8 + acol];
        A[mt][1] = sgin[(r + 8) * 100 + kit * 8 + acol];
        A[mt][2] = sgin[r * 100 + kit * 8 + acol + 4];
        A[mt][3] = sgin[(r + 8) * 100 + kit * 8 + acol + 4];
      }
      ull wv1 = W11[kit * 32 + lane];
      ull wv2 = W12[kit * 32 + lane];
#pragma unroll
      for (int mt = 0; mt < 4; mt++) {
        mma_f16(a1[mt], A[mt], (unsigned)wv1, (unsigned)(wv1 >> 32));
        mma_f16(g1[mt], A[mt], (unsigned)wv2, (unsigned)(wv2 >> 32));
      }
    }
#pragma unroll
    for (int mt = 0; mt < 4; mt++) {
      int r0 = mt * 16 + rq;
      stu[r0 * 36 + wa * 4 + acol] = h2pk(gelu_exact(a1[mt][0]) * g1[mt][0],
                                          gelu_exact(a1[mt][1]) * g1[mt][1]);
      stu[(r0 + 8) * 36 + wa * 4 + acol] = h2pk(gelu_exact(a1[mt][2]) * g1[mt][2],
                                                gelu_exact(a1[mt][3]) * g1[mt][3]);
    }
    __syncthreads();
    // ---- GEGLU GEMM2 -> write y directly into conv A-tile (sya) ----
    float y2[4][4];
    {
      int o = wa * 8 + 2 * acol;
      float b0 = b2[e * 64 + o], b1v = b2[e * 64 + o + 1];
#pragma unroll
      for (int mt = 0; mt < 4; mt++) {
        y2[mt][0] = b0; y2[mt][1] = b1v; y2[mt][2] = b0; y2[mt][3] = b1v;
      }
    }
    const ull* W2 = g_wp2 + e * 1024 + wa * 4 * 32;
    for (int kit = 0; kit < 4; kit++) {
      unsigned A[4][4];
#pragma unroll
      for (int mt = 0; mt < 4; mt++) {
        int r = mt * 16 + rq;
        A[mt][0] = stu[r * 36 + kit * 8 + acol];
        A[mt][1] = stu[(r + 8) * 36 + kit * 8 + acol];
        A[mt][2] = stu[r * 36 + kit * 8 + acol + 4];
        A[mt][3] = stu[(r + 8) * 36 + kit * 8 + acol + 4];
      }
      ull wv = W2[kit * 32 + lane];
#pragma unroll
      for (int mt = 0; mt < 4; mt++)
        mma_f16(y2[mt], A[mt], (unsigned)wv, (unsigned)(wv >> 32));
    }
    int kkb = e * 32 + wa * 4 + acol;
#pragma unroll
    for (int mt = 0; mt < 4; mt++) {
      int r0 = mt * 16 + rq;
      sya[r0 * 100 + kkb] = h2pk(y2[mt][0], y2[mt][1]);
      sya[(r0 + 8) * 100 + kkb] = h2pk(y2[mt][2], y2[mt][3]);
    }
    __syncthreads();
  }
  // ---- conv1x1 (192x192) over the assembled y tile ----
  float acc[3][4][4];
#pragma unroll
  for (int j = 0; j < 3; j++)
#pragma unroll
    for (int mt = 0; mt < 4; mt++)
#pragma unroll
      for (int r = 0; r < 4; r++) acc[j][mt][r] = 0.f;
  for (int kit = 0; kit < 12; kit++) {
    unsigned A[4][4];
#pragma unroll
    for (int mt = 0; mt < 4; mt++) {
      int r = mt * 16 + rq;
      A[mt][0] = sya[r * 100 + kit * 8 + acol];
      A[mt][1] = sya[(r + 8) * 100 + kit * 8 + acol];
      A[mt][2] = sya[r * 100 + kit * 8 + acol + 4];
      A[mt][3] = sya[(r + 8) * 100 + kit * 8 + acol + 4];
    }
#pragma unroll
    for (int j = 0; j < 3; j++) {
      ull wv = g_wp192[((wa * 3 + j) * 12 + kit) * 32 + lane];
#pragma unroll
      for (int mt = 0; mt < 4; mt++)
        mma_f16(acc[j][mt], A[mt], (unsigned)wv, (unsigned)(wv >> 32));
    }
  }
  __syncthreads();   // sya fully consumed; sres may alias it now
  int ccol0 = 2 * acol;
#pragma unroll
  for (int j = 0; j < 3; j++) {
    int oc = (wa * 3 + j) * 8 + ccol0;
#pragma unroll
    for (int mt = 0; mt < 4; mt++) {
      int r0 = mt * 16 + rq;
      sres[oc * 65 + r0] = acc[j][mt][0];
      sres[(oc + 1) * 65 + r0] = acc[j][mt][1];
      sres[oc * 65 + r0 + 8] = acc[j][mt][2];
      sres[(oc + 1) * 65 + r0 + 8] = acc[j][mt][3];
    }
  }
  __syncthreads();
  for (int idx = t; idx < 12288; idx += 256) {
    int n = idx & 63, oc = idx >> 6;
    int i = n >> 3, j = n & 7;
    int hp = (wh * 8 + i + 4) & 255;
    int wp = (ww * 8 + j + 4) & 255;
    int gi = oc * 65536 + hp * 256 + wp;
    g_xres[gi] = sres[oc * 65 + n] + x[gi];
  }
}

// ---------------- K5: LN2 + ff_in (192->768) fp16 MMA ------------------------------
// dyn f32[14848]: sxn [64][196] @0 (dies) | sxh u32 [64][100] @0 (in-place) | sfl @6400
__global__ void k5_ln_ffin(const float* __restrict__ ln2w, const float* __restrict__ ln2b) {
  extern __shared__ float sm5[];
  float* sxn = sm5;
  unsigned* sxh = (unsigned*)sm5;
  float* sfl = sm5 + 6400;
  __shared__ float red[256], red2[256], smean[64], srstd[64];
  int blk = blockIdx.x;
  int h = blk >> 2;
  int w0 = (blk & 3) * 64;
  int pix0 = h * 256 + w0;
  int t = threadIdx.x;
  for (int idx = t; idx < 12288; idx += 256) {
    int c = idx >> 6, p = idx & 63;
    sxn[p * 196 + c] = g_xres[c * 65536 + pix0 + p];
  }
  __syncthreads();
  {
    int p = t & 63, g = t >> 6;
    float s = 0.f, s2v = 0.f;
    for (int c = g; c < 192; c += 4) { float v = sxn[p * 196 + c]; s += v; s2v += v * v; }
    red[t] = s;
    red2[t] = s2v;
  }
  __syncthreads();
  if (t < 64) {
    float s = red[t] + red[64 + t] + red[128 + t] + red[192 + t];
    float s2v = red2[t] + red2[64 + t] + red2[128 + t] + red2[192 + t];
    float m = s * (1.f / 192.f);
    float var = s2v * (1.f / 192.f) - m * m;
    smean[t] = m;
    srstd[t] = rsqrtf(var + 1e-5f);
  }
  __syncthreads();
  // in-place f32 -> fp16 conversion via register staging (sxh aliases sxn)
  unsigned tmp[24];
#pragma unroll
  for (int k = 0; k < 24; k++) {
    int idx = t + k * 256;
    int p = idx / 96, kk = idx - p * 96;
    int c = kk * 2;
    float v0 = (sxn[p * 196 + c] - smean[p]) * srstd[p] * ln2w[c] + ln2b[c];
    float v1 = (sxn[p * 196 + c + 1] - smean[p]) * srstd[p] * ln2w[c + 1] + ln2b[c + 1];
    tmp[k] = h2pk(v0, v1);
  }
  __syncthreads();
#pragma unroll
  for (int k = 0; k < 24; k++) {
    int idx = t + k * 256;
    int p = idx / 96, kk = idx - p * 96;
    sxh[p * 100 + kk] = tmp[k];
  }
  __syncthreads();
  int wa = t >> 5, lane = t & 31;
  int rq = lane >> 2, acol = lane & 3, ccol0 = 2 * acol;
  for (int ch = 0; ch < 6; ch++) {
    float acc[2][4][4];
#pragma unroll
    for (int j = 0; j < 2; j++)
#pragma unroll
      for (int mt = 0; mt < 4; mt++)
#pragma unroll
        for (int r = 0; r < 4; r++) acc[j][mt][r] = 0.f;
    for (int kit = 0; kit < 12; kit++) {
      unsigned A[4][4];
#pragma unroll
      for (int mt = 0; mt < 4; mt++) {
        int r = mt * 16 + rq;
        A[mt][0] = sxh[r * 100 + kit * 8 + acol];
        A[mt][1] = sxh[(r + 8) * 100 + kit * 8 + acol];
        A[mt][2] = sxh[r * 100 + kit * 8 + acol + 4];
        A[mt][3] = sxh[(r + 8) * 100 + kit * 8 + acol + 4];
      }
#pragma unroll
      for (int j = 0; j < 2; j++) {
        int nt = wa * 12 + ch * 2 + j;
        ull wv = g_wp_in[(nt * 12 + kit) * 32 + lane];
#pragma unroll
        for (int mt = 0; mt < 4; mt++)
          mma_f16(acc[j][mt], A[mt], (unsigned)wv, (unsigned)(wv >> 32));
      }
    }
#pragma unroll
    for (int j = 0; j < 2; j++) {
      int lc = (wa * 2 + j) * 8 + ccol0;
#pragma unroll
      for (int mt = 0; mt < 4; mt++) {
        int r0 = mt * 16 + rq;
        sfl[lc * 66 + r0] = acc[j][mt][0];
        sfl[(lc + 1) * 66 + r0] = acc[j][mt][1];
        sfl[lc * 66 + r0 + 8] = acc[j][mt][2];
        sfl[(lc + 1) * 66 + r0 + 8] = acc[j][mt][3];
      }
    }
    __syncthreads();
    for (int idx = t; idx < 4096; idx += 256) {
      int lc = idx >> 5, p2 = (idx & 31) * 2;
      int o = ((lc >> 4) * 12 + ch * 2 + ((lc >> 3) & 1)) * 8 + (lc & 7);
      *(__half2*)&g_hbh[(long)o * 65536 + pix0 + p2] =
          __floats2half2_rn(sfl[lc * 66 + p2], sfl[lc * 66 + p2 + 1]);
    }
    __syncthreads();
  }
}

// ---------------- K6: depthwise 3x3 + gelu(g1)*g2, 16 rows/block, half2 ------------
__global__ void k6_dw(const float* __restrict__ dw) {
  __shared__ float s0[18][264];
  __shared__ float s1[18][264];
  int h0 = blockIdx.x * 16;
  int c = blockIdx.y;
  int t = threadIdx.x;
  const __half* p0 = g_hbh + (long)c * 65536;
  const __half* p1 = g_hbh + (long)(c + 384) * 65536;
  for (int idx = t; idx < 18 * 128; idx += 256) {
    int r = idx >> 7, cc = idx & 127;
    int hh = h0 - 1 + r;
    float2 v0 = make_float2(0.f, 0.f), v1 = make_float2(0.f, 0.f);
    if (hh >= 0 && hh < 256) {
      v0 = __half22float2(*(const __half2*)&p0[hh * 256 + cc * 2]);
      v1 = __half22float2(*(const __half2*)&p1[hh * 256 + cc * 2]);
    }
    s0[r][1 + 2 * cc] = v0.x;
    s0[r][2 + 2 * cc] = v0.y;
    s1[r][1 + 2 * cc] = v1.x;
    s1[r][2 + 2 * cc] = v1.y;
  }
  if (t < 18) { s0[t][0] = 0.f; s0[t][257] = 0.f; s1[t][0] = 0.f; s1[t][257] = 0.f; }
  float f0r[9], f1r[9];
#pragma unroll
  for (int k = 0; k < 9; k++) { f0r[k] = dw[c * 9 + k]; f1r[k] = dw[(c + 384) * 9 + k]; }
  __syncthreads();
  int cp = (t & 127) * 2;
  int rg = t >> 7;
#pragma unroll
  for (int r = 0; r < 8; r++) {
    int row = rg * 8 + r;
    float a0 = 0.f, b0 = 0.f, a1 = 0.f, b1 = 0.f;
#pragma unroll
    for (int dh = 0; dh < 3; dh++) {
#pragma unroll
      for (int dwi = 0; dwi < 3; dwi++) {
        float w = f0r[dh * 3 + dwi];
        float wv = f1r[dh * 3 + dwi];
        a0 += s0[row + dh][cp + dwi] * w;
        a1 += s0[row + dh][cp + 1 + dwi] * w;
        b0 += s1[row + dh][cp + dwi] * wv;
        b1 += s1[row + dh][cp + 1 + dwi] * wv;
      }
    }
    float o0 = gelu_exact(a0) * b0;
    float o1 = gelu_exact(a1) * b1;
    *(__half2*)&g_gbh[(long)c * 65536 + (h0 + row) * 256 + cp] = __floats2half2_rn(o0, o1);
  }
}

// ---------------- K7: ff_out (384->192) + residual, fp16 MMA -----------------------
// staging: vectorized pixel-quad loads (LDG.64) + PRMT channel-pair packing
__global__ void k7_ffout(float* __restrict__ out) {
  extern __shared__ unsigned sA[];
  __shared__ float sfl2[192 * 34];
  int blk = blockIdx.x;
  int h = blk >> 3;
  int w0 = (blk & 7) * 32;
  int pix0 = h * 256 + w0;
  int t = threadIdx.x;
  for (int idx = t; idx < 1536; idx += 256) {
    int pp = (idx & 7) * 4;          // pixel quad base 0,4,...,28
    int kk = idx >> 3;               // 0..191 (channel pair)
    int c = kk * 2;
    uint2 X = *(const uint2*)&g_gbh[(long)c * 65536 + pix0 + pp];
    uint2 Y = *(const uint2*)&g_gbh[(long)(c + 1) * 65536 + pix0 + pp];
    sA[pp * 196 + kk] = __byte_perm(X.x, Y.x, 0x5410);
    sA[(pp + 1) * 196 + kk] = __byte_perm(X.x, Y.x, 0x7632);
    sA[(pp + 2) * 196 + kk] = __byte_perm(X.y, Y.y, 0x5410);
    sA[(pp + 3) * 196 + kk] = __byte_perm(X.y, Y.y, 0x7632);
  }
  __syncthreads();
  int wa = t >> 5, lane = t & 31;
  int rq = lane >> 2, acol = lane & 3, ccol0 = 2 * acol;
  float acc[3][2][4];
#pragma unroll
  for (int j = 0; j < 3; j++)
#pragma unroll
    for (int mt = 0; mt < 2; mt++)
#pragma unroll
      for (int r = 0; r < 4; r++) acc[j][mt][r] = 0.f;
  for (int kit = 0; kit < 24; kit++) {
    unsigned A[2][4];
#pragma unroll
    for (int mt = 0; mt < 2; mt++) {
      int r = mt * 16 + rq;
      A[mt][0] = sA[r * 196 + kit * 8 + acol];
      A[mt][1] = sA[(r + 8) * 196 + kit * 8 + acol];
      A[mt][2] = sA[r * 196 + kit * 8 + acol + 4];
      A[mt][3] = sA[(r + 8) * 196 + kit * 8 + acol + 4];
    }
#pragma unroll
    for (int j = 0; j < 3; j++) {
      ull wv = g_wp_out[((wa * 3 + j) * 24 + kit) * 32 + lane];
#pragma unroll
      for (int mt = 0; mt < 2; mt++)
        mma_f16(acc[j][mt], A[mt], (unsigned)wv, (unsigned)(wv >> 32));
    }
  }
#pragma unroll
  for (int j = 0; j < 3; j++) {
    int oc = (wa * 3 + j) * 8 + ccol0;
#pragma unroll
    for (int mt = 0; mt < 2; mt++) {
      int r0 = mt * 16 + rq;
      sfl2[oc * 34 + r0] = acc[j][mt][0];
      sfl2[(oc + 1) * 34 + r0] = acc[j][mt][1];
      sfl2[oc * 34 + r0 + 8] = acc[j][mt][2];
      sfl2[(oc + 1) * 34 + r0 + 8] = acc[j][mt][3];
    }
  }
  __syncthreads();
  for (int idx = t; idx < 6144; idx += 256) {
    int oc = idx >> 5, p = idx & 31;
    int gi = oc * 65536 + pix0 + p;
    out[gi] = g_xres[gi] + sfl2[oc * 34 + p];
  }
}

// ---------------- host launcher ----------------------------------------------------
extern "C" void kernel_launch(void* const* d_in, const int* in_sizes, int n_in,
                              void* d_out, int out_size) {
  const float* x    = (const float*)d_in[0];
  const float* ln1w = (const float*)d_in[1];
  const float* ln1b = (const float*)d_in[2];
  const float* ln2w = (const float*)d_in[3];
  const float* ln2b = (const float*)d_in[4];
  const float* wqkv = (const float*)d_in[5];
  const float* w11  = (const float*)d_in[6];
  const float* b11  = (const float*)d_in[7];
  const float* w12  = (const float*)d_in[8];
  const float* b12  = (const float*)d_in[9];
  const float* w2   = (const float*)d_in[10];
  const float* b2   = (const float*)d_in[11];
  const float* c11  = (const float*)d_in[12];
  const float* ffin = (const float*)d_in[13];
  const float* ffdw = (const float*)d_in[14];
  const float* ffou = (const float*)d_in[15];
  float* out = (float*)d_out;

  const int smem1 = 192 * 65 * 4;                 // 49920
  const int smem234 = 12800 * 4;                  // 51200
  const int smem5 = 14848 * 4;                    // 59392
  const int smem7 = 32 * 196 * 4;                 // 25088
  cudaFuncSetAttribute(k1_qkv, cudaFuncAttributeMaxDynamicSharedMemorySize, smem1);
  cudaFuncSetAttribute(k234_fused, cudaFuncAttributeMaxDynamicSharedMemorySize, smem234);
  cudaFuncSetAttribute(k5_ln_ffin, cudaFuncAttributeMaxDynamicSharedMemorySize, smem5);
  cudaFuncSetAttribute(k7_ffout, cudaFuncAttributeMaxDynamicSharedMemorySize, smem7);

  kpos<<<1, 64>>>();
  kpack<<<144, 256>>>(c11, ffin, ffou, w11, w12, w2, wqkv);
  k1_qkv<<<3072, 256, smem1>>>(x, ln1w, ln1b);
  k234_fused<<<1024, 256, smem234>>>(b11, b12, b2, x);
  k5_ln_ffin<<<1024, 256, smem5>>>(ln2w, ln2b);
  {
    dim3 g6(16, 384);
    k6_dw<<<g6, 256>>>(ffdw);
  }
  k7_ffout<<<2048, 256, smem7>>>(out);
}

// round 16
// speedup vs baseline: 1.0235x; 1.0091x over previous
#include <cuda_runtime.h>
#include <cuda_fp16.h>
#include <math.h>

typedef unsigned long long ull;

// ---------------- fp16 MMA helpers -------------------------------------------------
__device__ __forceinline__ unsigned h2pk(float a, float b) {
  __half2 h = __floats2half2_rn(a, b);
  return *(unsigned*)&h;
}
__device__ __forceinline__ void mma_f16(float* c, const unsigned* a, unsigned b0, unsigned b1) {
  asm volatile(
      "mma.sync.aligned.m16n8k16.row.col.f32.f16.f16.f32 "
      "{%0,%1,%2,%3},{%4,%5,%6,%7},{%8,%9},{%0,%1,%2,%3};"
      : "+f"(c[0]), "+f"(c[1]), "+f"(c[2]), "+f"(c[3])
      : "r"(a[0]), "r"(a[1]), "r"(a[2]), "r"(a[3]), "r"(b0), "r"(b1));
}
__device__ __forceinline__ float gelu_exact(float a) {
  return 0.5f * a * (1.f + erff(a * 0.70710678118654752f));
}

// ---------------- static device scratch --------------------------------------------
__device__ float g_pos[64 * 64];
__device__ __half g_qh[3 * 1024 * 4096];
__device__ __half g_ql[3 * 1024 * 4096];
__device__ __half g_kh[3 * 1024 * 4096];
__device__ __half g_kl[3 * 1024 * 4096];
__device__ __half g_vt[3 * 1024 * 4096];
__device__ float g_xres[192 * 65536];
__device__ __half g_hbh[768 * 65536];
__device__ __half g_gbh[384 * 65536];
// packed fp16 weight fragments: [ntile][kit16][lane] -> (b0 | b1<<32)
__device__ ull g_wp_in[96 * 12 * 32];     // ff_in  (K=192, N=768)
__device__ ull g_wp_out[24 * 24 * 32];    // ff_out (K=384, N=192)
__device__ ull g_wp11[3 * 8 * 12 * 32];   // me_w11 (K=192, N=64)
__device__ ull g_wp12[3 * 8 * 12 * 32];   // me_w12
__device__ ull g_wp2[3 * 8 * 4 * 32];     // me_w2  (K=64,  N=64)
__device__ ull g_wpqkv[24 * 4 * 32];      // w_qkv  (K=64,  N=192)
__device__ ull g_wp192[24 * 12 * 32];     // conv11 (K=192, N=192)

// ---------------- K0a: sine positional encoding ------------------------------------
__global__ void kpos() {
  int n = threadIdx.x;
  int i = n >> 3, j = n & 7;
  double scale = 6.283185307179586476925286766559;
  double yv = (double)(i + 1) / (8.0 + 1e-6) * scale;
  double xv = (double)(j + 1) / (8.0 + 1e-6) * scale;
  for (int c = 0; c < 64; c++) {
    double base = (c < 32) ? yv : xv;
    int k = (c < 32) ? c : (c - 32);
    double dt = pow(10000.0, (double)(k >> 1) / 16.0);
    double v = base / dt;
    g_pos[n * 64 + c] = (float)(((k & 1) == 0) ? sin(v) : cos(v));
  }
}

// ---------------- K0b: fp16 fragment packing ---------------------------------------
__global__ void kpack(const float* __restrict__ c11, const float* __restrict__ ffin,
                      const float* __restrict__ ffout, const float* __restrict__ w11,
                      const float* __restrict__ w12, const float* __restrict__ w2,
                      const float* __restrict__ wqkv) {
  int idx = blockIdx.x * 256 + threadIdx.x;
  int lane = idx & 31;
  if (idx < 36864) {  // wp_in [96][12][32], src [o=768][k=192]
    int kit = (idx >> 5) % 12, nt = idx / 384;
    int o = nt * 8 + (lane >> 2), k0 = kit * 16 + (lane & 3) * 2;
    unsigned b0 = h2pk(ffin[o * 192 + k0], ffin[o * 192 + k0 + 1]);
    unsigned b1 = h2pk(ffin[o * 192 + k0 + 8], ffin[o * 192 + k0 + 9]);
    g_wp_in[idx] = (ull)b0 | ((ull)b1 << 32);
  }
  if (idx < 18432) {  // wp_out [24][24][32], src [o=192][k=384]
    int kit = (idx >> 5) % 24, nt = idx / 768;
    int o = nt * 8 + (lane >> 2), k0 = kit * 16 + (lane & 3) * 2;
    unsigned b0 = h2pk(ffout[o * 384 + k0], ffout[o * 384 + k0 + 1]);
    unsigned b1 = h2pk(ffout[o * 384 + k0 + 8], ffout[o * 384 + k0 + 9]);
    g_wp_out[idx] = (ull)b0 | ((ull)b1 << 32);
  }
  if (idx < 9216) {  // wp11/wp12 [3][8][12][32], src [e][k=192][f=64]
    int e = idx / 3072, r = idx % 3072;
    int kit = (r >> 5) % 12, nt = r / 384;
    int f = nt * 8 + (lane >> 2), k0 = kit * 16 + (lane & 3) * 2;
    const float* Wa = w11 + e * 12288;
    const float* Wb = w12 + e * 12288;
    unsigned a0 = h2pk(Wa[k0 * 64 + f], Wa[(k0 + 1) * 64 + f]);
    unsigned a1 = h2pk(Wa[(k0 + 8) * 64 + f], Wa[(k0 + 9) * 64 + f]);
    g_wp11[idx] = (ull)a0 | ((ull)a1 << 32);
    unsigned c0 = h2pk(Wb[k0 * 64 + f], Wb[(k0 + 1) * 64 + f]);
    unsigned c1 = h2pk(Wb[(k0 + 8) * 64 + f], Wb[(k0 + 9) * 64 + f]);
    g_wp12[idx] = (ull)c0 | ((ull)c1 << 32);
  }
  if (idx < 3072) {  // wp2 [3][8][4][32], src [e][k=64][f=64]
    int e = idx / 1024, r = idx % 1024;
    int kit = (r >> 5) % 4, nt = r / 128;
    int f = nt * 8 + (lane >> 2), k0 = kit * 16 + (lane & 3) * 2;
    const float* Wa = w2 + e * 4096;
    unsigned b0 = h2pk(Wa[k0 * 64 + f], Wa[(k0 + 1) * 64 + f]);
    unsigned b1 = h2pk(Wa[(k0 + 8) * 64 + f], Wa[(k0 + 9) * 64 + f]);
    g_wp2[idx] = (ull)b0 | ((ull)b1 << 32);
  }
  if (idx < 3072) {  // wpqkv [24][4][32], src [k=64][n=192]
    int kit = (idx >> 5) % 4, nt = idx / 128;
    int n = nt * 8 + (lane >> 2), k0 = kit * 16 + (lane & 3) * 2;
    unsigned b0 = h2pk(wqkv[k0 * 192 + n], wqkv[(k0 + 1) * 192 + n]);
    unsigned b1 = h2pk(wqkv[(k0 + 8) * 192 + n], wqkv[(k0 + 9) * 192 + n]);
    g_wpqkv[idx] = (ull)b0 | ((ull)b1 << 32);
  }
  if (idx < 9216) {  // wp192 [24][12][32], src [o=192][k=192]
    int kit = (idx >> 5) % 12, nt = idx / 384;
    int o = nt * 8 + (lane >> 2), k0 = kit * 16 + (lane & 3) * 2;
    unsigned b0 = h2pk(c11[o * 192 + k0], c11[o * 192 + k0 + 1]);
    unsigned b1 = h2pk(c11[o * 192 + k0 + 8], c11[o * 192 + k0 + 9]);
    g_wp192[idx] = (ull)b0 | ((ull)b1 << 32);
  }
}

// ---------------- K1: shift+window + LN1 + pos + QKV GEMM (fp16 MMA) ---------------
__global__ void k1_qkv(const float* __restrict__ x, const float* __restrict__ ln1w,
                       const float* __restrict__ ln1b) {
  extern __shared__ float sm1[];
  float* sx = sm1;
  unsigned* snT = (unsigned*)(sm1 + 4160);
  float* sout = sm1;
  __shared__ float smean[64], srstd[64];
  int blk = blockIdx.x;
  int e = blk >> 10, wwin = blk & 1023;
  int wh = wwin >> 5, ww = wwin & 31;
  int t = threadIdx.x;
  for (int idx = t; idx < 4096; idx += 256) {
    int c = idx >> 6, n = idx & 63;
    int i = n >> 3, j = n & 7;
    int h0 = (wh * 8 + i + 4) & 255;
    int w0 = (ww * 8 + j + 4) & 255;
    sx[n * 65 + c] = x[((e * 64 + c) * 256 + h0) * 256 + w0];
  }
  __syncthreads();
  if (t < 64) {
    int n = t;
    float m = 0.f;
#pragma unroll
    for (int c = 0; c < 64; c++) m += sx[n * 65 + c];
    m *= (1.f / 64.f);
    float v = 0.f;
#pragma unroll
    for (int c = 0; c < 64; c++) { float d = sx[n * 65 + c] - m; v += d * d; }
    v *= (1.f / 64.f);
    smean[n] = m;
    srstd[n] = rsqrtf(v + 1e-5f);
  }
  __syncthreads();
  for (int idx = t; idx < 2048; idx += 256) {
    int n = idx >> 5, kk = idx & 31;
    int c = kk * 2;
    float v0 = (sx[n * 65 + c] - smean[n]) * srstd[n] * ln1w[c] + ln1b[c] + g_pos[n * 64 + c];
    float v1 = (sx[n * 65 + c + 1] - smean[n]) * srstd[n] * ln1w[c + 1] + ln1b[c + 1] + g_pos[n * 64 + c + 1];
    snT[n * 36 + kk] = h2pk(v0, v1);
  }
  __syncthreads();
  int wa = t >> 5, lane = t & 31;
  int rq = lane >> 2, acol = lane & 3, ccol0 = 2 * acol;
  float acc[3][4][4];
#pragma unroll
  for (int j = 0; j < 3; j++)
#pragma unroll
    for (int mt = 0; mt < 4; mt++)
#pragma unroll
      for (int r = 0; r < 4; r++) acc[j][mt][r] = 0.f;
  for (int kit = 0; kit < 4; kit++) {
    unsigned A[4][4];
#pragma unroll
    for (int mt = 0; mt < 4; mt++) {
      int r = mt * 16 + rq;
      A[mt][0] = snT[r * 36 + kit * 8 + acol];
      A[mt][1] = snT[(r + 8) * 36 + kit * 8 + acol];
      A[mt][2] = snT[r * 36 + kit * 8 + acol + 4];
      A[mt][3] = snT[(r + 8) * 36 + kit * 8 + acol + 4];
    }
#pragma unroll
    for (int j = 0; j < 3; j++) {
      ull wv = g_wpqkv[((wa * 3 + j) * 4 + kit) * 32 + lane];
#pragma unroll
      for (int mt = 0; mt < 4; mt++)
        mma_f16(acc[j][mt], A[mt], (unsigned)wv, (unsigned)(wv >> 32));
    }
  }
  __syncthreads();
#pragma unroll
  for (int j = 0; j < 3; j++) {
    int jc = (wa * 3 + j) * 8 + ccol0;
#pragma unroll
    for (int mt = 0; mt < 4; mt++) {
      int r0 = mt * 16 + rq;
      sout[jc * 65 + r0] = acc[j][mt][0];
      sout[(jc + 1) * 65 + r0] = acc[j][mt][1];
      sout[jc * 65 + r0 + 8] = acc[j][mt][2];
      sout[(jc + 1) * 65 + r0 + 8] = acc[j][mt][3];
    }
  }
  __syncthreads();
  long wb = (long)(e * 1024 + wwin);
  // q/k: hi/lo fp16 split, half2-vectorized (channel pairs)
  for (int idx = t; idx < 4096; idx += 256) {
    int ch2 = idx & 7, n = (idx >> 3) & 63, hh = (idx >> 9) & 3, p = idx >> 11;
    int c0 = ch2 * 2;
    float vv0 = sout[(p * 64 + c0 * 4 + hh) * 65 + n];
    float vv1 = sout[(p * 64 + (c0 + 1) * 4 + hh) * 65 + n];
    __half h0 = __float2half_rn(vv0), h1 = __float2half_rn(vv1);
    __half2 hi = __halves2half2(h0, h1);
    __half2 lo = __floats2half2_rn(vv0 - __half2float(h0), vv1 - __half2float(h1));
    long qi = (wb * 4 + hh) * 1024 + n * 16 + c0;
    if (p == 0) {
      *(__half2*)&g_qh[qi] = hi;
      *(__half2*)&g_ql[qi] = lo;
    } else {
      *(__half2*)&g_kh[qi] = hi;
      *(__half2*)&g_kl[qi] = lo;
    }
  }
  // v: fp16 transposed [hh][ch][n], half2-vectorized (key pairs)
  for (int idx = t; idx < 2048; idx += 256) {
    int n2 = idx & 31, co = idx >> 5;
    int hh = co & 3, ch = co >> 2;
    float vv0 = sout[(128 + co) * 65 + 2 * n2];
    float vv1 = sout[(128 + co) * 65 + 2 * n2 + 1];
    *(__half2*)&g_vt[(wb * 4 + hh) * 1024 + ch * 64 + 2 * n2] = __floats2half2_rn(vv0, vv1);
  }
}

// ---------------- K234: fused 3-exposure attention + GEGLU + conv1x1 + residual ----
// dyn smem u32[13056]: sgin[64][100] @0 | sya[64][100] @6400; sres f32 [192][68] aliases.
__device__ __forceinline__ ull maskw(int row, int wh, int ww) {
  ull m = 0ULL;
  if (wh == 31) m |= ((row >> 3) < 4) ? 0xFFFFFFFF00000000ULL : 0x00000000FFFFFFFFULL;
  if (ww == 31) m |= ((row & 7) < 4) ? 0xF0F0F0F0F0F0F0F0ULL : 0x0F0F0F0F0F0F0F0FULL;
  return m;
}

__global__ void __launch_bounds__(256, 2)
k234_fused(const float* __restrict__ b11, const float* __restrict__ b12,
           const float* __restrict__ b2, const float* __restrict__ x) {
  extern __shared__ unsigned smu[];
  unsigned* sgin = smu;          // [64][100]
  unsigned* sya = smu + 6400;    // [64][100] conv A-tile
  float* sres = (float*)smu;     // [192][68] alias; used after conv MMA
  __shared__ unsigned stu[64 * 36];
  int w = blockIdx.x;
  int wh = w >> 5, ww = w & 31;
  const int ekvA_of[3] = {1, 0, 1};
  const int ekvB_of[3] = {2, 2, 0};
  int t = threadIdx.x;
  int wa = t >> 5, lane = t & 31;
  int rq = lane >> 2, acol = lane & 3;
  int slot = wa >> 2, hh = wa & 3;
  for (int e = 0; e < 3; e++) {
    long qb = (long)(e * 1024 + w) * 4096;
    // --- phase1: merged-q copy + attention (both write disjoint sgin regions) ---
    for (int idx = t; idx < 1024; idx += 256) {
      int n = idx >> 4, pr = idx & 15;
      int hh2 = pr >> 2, c2 = (pr & 3) * 4;
      uint2 qv = *(const uint2*)&g_qh[qb + hh2 * 1024 + n * 16 + c2];
      sgin[n * 100 + 64 + pr * 2] = qv.x;
      sgin[n * 100 + 64 + pr * 2 + 1] = qv.y;
    }
    {
      int ekv = slot ? ekvB_of[e] : ekvA_of[e];
      long kb = ((long)(ekv * 1024 + w) * 4 + hh) * 1024;
      long qhb = qb + hh * 1024;
      unsigned Kfh[8][2], Kfl[8][2];
#pragma unroll
      for (int nt = 0; nt < 8; nt++) {
        int row = nt * 8 + rq;
        Kfh[nt][0] = *(const unsigned*)&g_kh[kb + row * 16 + 2 * acol];
        Kfh[nt][1] = *(const unsigned*)&g_kh[kb + row * 16 + 8 + 2 * acol];
        Kfl[nt][0] = *(const unsigned*)&g_kl[kb + row * 16 + 2 * acol];
        Kfl[nt][1] = *(const unsigned*)&g_kl[kb + row * 16 + 8 + 2 * acol];
      }
      unsigned Vf[4][2][2];
#pragma unroll
      for (int kit = 0; kit < 4; kit++)
#pragma unroll
        for (int n2 = 0; n2 < 2; n2++) {
          Vf[kit][n2][0] = *(const unsigned*)&g_vt[kb + (n2 * 8 + rq) * 64 + (kit * 8 + acol) * 2];
          Vf[kit][n2][1] = *(const unsigned*)&g_vt[kb + (n2 * 8 + rq) * 64 + (kit * 8 + 4 + acol) * 2];
        }
#pragma unroll
      for (int mt = 0; mt < 4; mt++) {
        int r0 = mt * 16 + rq;
        unsigned Ah[4], Al[4];
        Ah[0] = *(const unsigned*)&g_qh[qhb + r0 * 16 + 2 * acol];
        Ah[1] = *(const unsigned*)&g_qh[qhb + (r0 + 8) * 16 + 2 * acol];
        Ah[2] = *(const unsigned*)&g_qh[qhb + r0 * 16 + 8 + 2 * acol];
        Ah[3] = *(const unsigned*)&g_qh[qhb + (r0 + 8) * 16 + 8 + 2 * acol];
        Al[0] = *(const unsigned*)&g_ql[qhb + r0 * 16 + 2 * acol];
        Al[1] = *(const unsigned*)&g_ql[qhb + (r0 + 8) * 16 + 2 * acol];
        Al[2] = *(const unsigned*)&g_ql[qhb + r0 * 16 + 8 + 2 * acol];
        Al[3] = *(const unsigned*)&g_ql[qhb + (r0 + 8) * 16 + 8 + 2 * acol];
        float sc[8][4];
#pragma unroll
        for (int nt = 0; nt < 8; nt++) {
#pragma unroll
          for (int r = 0; r < 4; r++) sc[nt][r] = 0.f;
          mma_f16(sc[nt], Ah, Kfh[nt][0], Kfh[nt][1]);
          mma_f16(sc[nt], Ah, Kfl[nt][0], Kfl[nt][1]);
          mma_f16(sc[nt], Al, Kfh[nt][0], Kfh[nt][1]);
        }
        ull m0 = maskw(r0, wh, ww);
        ull m1 = maskw(r0 + 8, wh, ww);
        float sum0 = 0.f, sum1 = 0.f;
        unsigned Pf[4][4];
#pragma unroll
        for (int nt = 0; nt < 8; nt++) {
          int c0 = nt * 8 + 2 * acol;
          float p0 = ((m0 >> c0) & 1) ? 0.f : __expf(sc[nt][0] * 0.125f);
          float p1 = ((m0 >> (c0 + 1)) & 1) ? 0.f : __expf(sc[nt][1] * 0.125f);
          float p2 = ((m1 >> c0) & 1) ? 0.f : __expf(sc[nt][2] * 0.125f);
          float p3 = ((m1 >> (c0 + 1)) & 1) ? 0.f : __expf(sc[nt][3] * 0.125f);
          sum0 += p0 + p1;
          sum1 += p2 + p3;
          Pf[nt >> 1][(nt & 1) ? 2 : 0] = h2pk(p0, p1);
          Pf[nt >> 1][(nt & 1) ? 3 : 1] = h2pk(p2, p3);
        }
        sum0 += __shfl_xor_sync(0xFFFFFFFFu, sum0, 1);
        sum0 += __shfl_xor_sync(0xFFFFFFFFu, sum0, 2);
        sum1 += __shfl_xor_sync(0xFFFFFFFFu, sum1, 1);
        sum1 += __shfl_xor_sync(0xFFFFFFFFu, sum1, 2);
        float inv0 = 1.f / sum0, inv1 = 1.f / sum1;
        float oc[2][4];
#pragma unroll
        for (int n2 = 0; n2 < 2; n2++)
#pragma unroll
          for (int r = 0; r < 4; r++) oc[n2][r] = 0.f;
#pragma unroll
        for (int kit = 0; kit < 4; kit++)
#pragma unroll
          for (int n2 = 0; n2 < 2; n2++)
            mma_f16(oc[n2], Pf[kit], Vf[kit][n2][0], Vf[kit][n2][1]);
#pragma unroll
        for (int n2 = 0; n2 < 2; n2++) {
          int fb = slot * 32 + hh * 8 + n2 * 4 + acol;
          sgin[r0 * 100 + fb] = h2pk(oc[n2][0] * inv0, oc[n2][1] * inv0);
          sgin[(r0 + 8) * 100 + fb] = h2pk(oc[n2][2] * inv1, oc[n2][3] * inv1);
        }
      }
    }
    __syncthreads();
    // ---- GEGLU GEMM1 ----
    float a1[4][4], g1[4][4];
    {
      int o = wa * 8 + 2 * acol;
      float ba0 = b11[e * 64 + o], ba1 = b11[e * 64 + o + 1];
      float bg0 = b12[e * 64 + o], bg1 = b12[e * 64 + o + 1];
#pragma unroll
      for (int mt = 0; mt < 4; mt++) {
        a1[mt][0] = ba0; a1[mt][1] = ba1; a1[mt][2] = ba0; a1[mt][3] = ba1;
        g1[mt][0] = bg0; g1[mt][1] = bg1; g1[mt][2] = bg0; g1[mt][3] = bg1;
      }
    }
    const ull* W11 = g_wp11 + e * 3072 + wa * 12 * 32;
    const ull* W12 = g_wp12 + e * 3072 + wa * 12 * 32;
    for (int kit = 0; kit < 12; kit++) {
      unsigned A[4][4];
#pragma unroll
      for (int mt = 0; mt < 4; mt++) {
        int r = mt * 16 + rq;
        A[mt][0] = sgin[r * 100 + kit * 8 + acol];
        A[mt][1] = sgin[(r + 8) * 100 + kit * 8 + acol];
        A[mt][2] = sgin[r * 100 + kit * 8 + acol + 4];
        A[mt][3] = sgin[(r + 8) * 100 + kit * 8 + acol + 4];
      }
      ull wv1 = W11[kit * 32 + lane];
      ull wv2 = W12[kit * 32 + lane];
#pragma unroll
      for (int mt = 0; mt < 4; mt++) {
        mma_f16(a1[mt], A[mt], (unsigned)wv1, (unsigned)(wv1 >> 32));
        mma_f16(g1[mt], A[mt], (unsigned)wv2, (unsigned)(wv2 >> 32));
      }
    }
#pragma unroll
    for (int mt = 0; mt < 4; mt++) {
      int r0 = mt * 16 + rq;
      stu[r0 * 36 + wa * 4 + acol] = h2pk(gelu_exact(a1[mt][0]) * g1[mt][0],
                                          gelu_exact(a1[mt][1]) * g1[mt][1]);
      stu[(r0 + 8) * 36 + wa * 4 + acol] = h2pk(gelu_exact(a1[mt][2]) * g1[mt][2],
                                                gelu_exact(a1[mt][3]) * g1[mt][3]);
    }
    __syncthreads();
    // ---- GEGLU GEMM2 -> write y directly into conv A-tile (sya) ----
    float y2[4][4];
    {
      int o = wa * 8 + 2 * acol;
      float b0 = b2[e * 64 + o], b1v = b2[e * 64 + o + 1];
#pragma unroll
      for (int mt = 0; mt < 4; mt++) {
        y2[mt][0] = b0; y2[mt][1] = b1v; y2[mt][2] = b0; y2[mt][3] = b1v;
      }
    }
    const ull* W2 = g_wp2 + e * 1024 + wa * 4 * 32;
    for (int kit = 0; kit < 4; kit++) {
      unsigned A[4][4];
#pragma unroll
      for (int mt = 0; mt < 4; mt++) {
        int r = mt * 16 + rq;
        A[mt][0] = stu[r * 36 + kit * 8 + acol];
        A[mt][1] = stu[(r + 8) * 36 + kit * 8 + acol];
        A[mt][2] = stu[r * 36 + kit * 8 + acol + 4];
        A[mt][3] = stu[(r + 8) * 36 + kit * 8 + acol + 4];
      }
      ull wv = W2[kit * 32 + lane];
#pragma unroll
      for (int mt = 0; mt < 4; mt++)
        mma_f16(y2[mt], A[mt], (unsigned)wv, (unsigned)(wv >> 32));
    }
    int kkb = e * 32 + wa * 4 + acol;
#pragma unroll
    for (int mt = 0; mt < 4; mt++) {
      int r0 = mt * 16 + rq;
      sya[r0 * 100 + kkb] = h2pk(y2[mt][0], y2[mt][1]);
      sya[(r0 + 8) * 100 + kkb] = h2pk(y2[mt][2], y2[mt][3]);
    }
    __syncthreads();
  }
  // ---- conv1x1 (192x192) over the assembled y tile ----
  float acc[3][4][4];
#pragma unroll
  for (int j = 0; j < 3; j++)
#pragma unroll
    for (int mt = 0; mt < 4; mt++)
#pragma unroll
      for (int r = 0; r < 4; r++) acc[j][mt][r] = 0.f;
  for (int kit = 0; kit < 12; kit++) {
    unsigned A[4][4];
#pragma unroll
    for (int mt = 0; mt < 4; mt++) {
      int r = mt * 16 + rq;
      A[mt][0] = sya[r * 100 + kit * 8 + acol];
      A[mt][1] = sya[(r + 8) * 100 + kit * 8 + acol];
      A[mt][2] = sya[r * 100 + kit * 8 + acol + 4];
      A[mt][3] = sya[(r + 8) * 100 + kit * 8 + acol + 4];
    }
#pragma unroll
    for (int j = 0; j < 3; j++) {
      ull wv = g_wp192[((wa * 3 + j) * 12 + kit) * 32 + lane];
#pragma unroll
      for (int mt = 0; mt < 4; mt++)
        mma_f16(acc[j][mt], A[mt], (unsigned)wv, (unsigned)(wv >> 32));
    }
  }
  __syncthreads();   // sya fully consumed; sres may alias it now
  int ccol0 = 2 * acol;
#pragma unroll
  for (int j = 0; j < 3; j++) {
    int oc = (wa * 3 + j) * 8 + ccol0;
#pragma unroll
    for (int mt = 0; mt < 4; mt++) {
      int r0 = mt * 16 + rq;
      sres[oc * 68 + r0] = acc[j][mt][0];
      sres[(oc + 1) * 68 + r0] = acc[j][mt][1];
      sres[oc * 68 + r0 + 8] = acc[j][mt][2];
      sres[(oc + 1) * 68 + r0 + 8] = acc[j][mt][3];
    }
  }
  __syncthreads();
  // vectorized residual epilogue: pixel quads are contiguous even under the roll
  for (int idx = t; idx < 3072; idx += 256) {
    int nq = (idx & 15) * 4;      // n quad base: 0,4,...,60
    int oc = idx >> 4;            // 0..191
    int i = nq >> 3, j = nq & 7;  // j in {0,4}; quad never crosses a window row
    int hp = (wh * 8 + i + 4) & 255;
    int wp = (ww * 8 + j + 4) & 255;
    int gi = oc * 65536 + hp * 256 + wp;
    float4 rv = *(const float4*)&x[gi];
    float4 sv = *(const float4*)&sres[oc * 68 + nq];
    *(float4*)&g_xres[gi] = make_float4(sv.x + rv.x, sv.y + rv.y, sv.z + rv.z, sv.w + rv.w);
  }
}

// ---------------- K5: LN2 + ff_in (192->768) fp16 MMA ------------------------------
// dyn f32[14848]: sxn [64][196] @0 (dies) | sxh u32 [64][100] @0 (in-place) | sfl @6400
__global__ void k5_ln_ffin(const float* __restrict__ ln2w, const float* __restrict__ ln2b) {
  extern __shared__ float sm5[];
  float* sxn = sm5;
  unsigned* sxh = (unsigned*)sm5;
  float* sfl = sm5 + 6400;
  __shared__ float red[256], red2[256], smean[64], srstd[64];
  int blk = blockIdx.x;
  int h = blk >> 2;
  int w0 = (blk & 3) * 64;
  int pix0 = h * 256 + w0;
  int t = threadIdx.x;
  for (int idx = t; idx < 12288; idx += 256) {
    int c = idx >> 6, p = idx & 63;
    sxn[p * 196 + c] = g_xres[c * 65536 + pix0 + p];
  }
  __syncthreads();
  {
    int p = t & 63, g = t >> 6;
    float s = 0.f, s2v = 0.f;
    for (int c = g; c < 192; c += 4) { float v = sxn[p * 196 + c]; s += v; s2v += v * v; }
    red[t] = s;
    red2[t] = s2v;
  }
  __syncthreads();
  if (t < 64) {
    float s = red[t] + red[64 + t] + red[128 + t] + red[192 + t];
    float s2v = red2[t] + red2[64 + t] + red2[128 + t] + red2[192 + t];
    float m = s * (1.f / 192.f);
    float var = s2v * (1.f / 192.f) - m * m;
    smean[t] = m;
    srstd[t] = rsqrtf(var + 1e-5f);
  }
  __syncthreads();
  // in-place f32 -> fp16 conversion via register staging (sxh aliases sxn)
  unsigned tmp[24];
#pragma unroll
  for (int k = 0; k < 24; k++) {
    int idx = t + k * 256;
    int p = idx / 96, kk = idx - p * 96;
    int c = kk * 2;
    float v0 = (sxn[p * 196 + c] - smean[p]) * srstd[p] * ln2w[c] + ln2b[c];
    float v1 = (sxn[p * 196 + c + 1] - smean[p]) * srstd[p] * ln2w[c + 1] + ln2b[c + 1];
    tmp[k] = h2pk(v0, v1);
  }
  __syncthreads();
#pragma unroll
  for (int k = 0; k < 24; k++) {
    int idx = t + k * 256;
    int p = idx / 96, kk = idx - p * 96;
    sxh[p * 100 + kk] = tmp[k];
  }
  __syncthreads();
  int wa = t >> 5, lane = t & 31;
  int rq = lane >> 2, acol = lane & 3, ccol0 = 2 * acol;
  for (int ch = 0; ch < 6; ch++) {
    float acc[2][4][4];
#pragma unroll
    for (int j = 0; j < 2; j++)
#pragma unroll
      for (int mt = 0; mt < 4; mt++)
#pragma unroll
        for (int r = 0; r < 4; r++) acc[j][mt][r] = 0.f;
    for (int kit = 0; kit < 12; kit++) {
      unsigned A[4][4];
#pragma unroll
      for (int mt = 0; mt < 4; mt++) {
        int r = mt * 16 + rq;
        A[mt][0] = sxh[r * 100 + kit * 8 + acol];
        A[mt][1] = sxh[(r + 8) * 100 + kit * 8 + acol];
        A[mt][2] = sxh[r * 100 + kit * 8 + acol + 4];
        A[mt][3] = sxh[(r + 8) * 100 + kit * 8 + acol + 4];
      }
#pragma unroll
      for (int j = 0; j < 2; j++) {
        int nt = wa * 12 + ch * 2 + j;
        ull wv = g_wp_in[(nt * 12 + kit) * 32 + lane];
#pragma unroll
        for (int mt = 0; mt < 4; mt++)
          mma_f16(acc[j][mt], A[mt], (unsigned)wv, (unsigned)(wv >> 32));
      }
    }
#pragma unroll
    for (int j = 0; j < 2; j++) {
      int lc = (wa * 2 + j) * 8 + ccol0;
#pragma unroll
      for (int mt = 0; mt < 4; mt++) {
        int r0 = mt * 16 + rq;
        sfl[lc * 66 + r0] = acc[j][mt][0];
        sfl[(lc + 1) * 66 + r0] = acc[j][mt][1];
        sfl[lc * 66 + r0 + 8] = acc[j][mt][2];
        sfl[(lc + 1) * 66 + r0 + 8] = acc[j][mt][3];
      }
    }
    __syncthreads();
    for (int idx = t; idx < 4096; idx += 256) {
      int lc = idx >> 5, p2 = (idx & 31) * 2;
      int o = ((lc >> 4) * 12 + ch * 2 + ((lc >> 3) & 1)) * 8 + (lc & 7);
      *(__half2*)&g_hbh[(long)o * 65536 + pix0 + p2] =
          __floats2half2_rn(sfl[lc * 66 + p2], sfl[lc * 66 + p2 + 1]);
    }
    __syncthreads();
  }
}

// ---------------- K6: depthwise 3x3 + gelu(g1)*g2, 16 rows/block, half2 ------------
__global__ void k6_dw(const float* __restrict__ dw) {
  __shared__ float s0[18][264];
  __shared__ float s1[18][264];
  int h0 = blockIdx.x * 16;
  int c = blockIdx.y;
  int t = threadIdx.x;
  const __half* p0 = g_hbh + (long)c * 65536;
  const __half* p1 = g_hbh + (long)(c + 384) * 65536;
  for (int idx = t; idx < 18 * 128; idx += 256) {
    int r = idx >> 7, cc = idx & 127;
    int hh = h0 - 1 + r;
    float2 v0 = make_float2(0.f, 0.f), v1 = make_float2(0.f, 0.f);
    if (hh >= 0 && hh < 256) {
      v0 = __half22float2(*(const __half2*)&p0[hh * 256 + cc * 2]);
      v1 = __half22float2(*(const __half2*)&p1[hh * 256 + cc * 2]);
    }
    s0[r][1 + 2 * cc] = v0.x;
    s0[r][2 + 2 * cc] = v0.y;
    s1[r][1 + 2 * cc] = v1.x;
    s1[r][2 + 2 * cc] = v1.y;
  }
  if (t < 18) { s0[t][0] = 0.f; s0[t][257] = 0.f; s1[t][0] = 0.f; s1[t][257] = 0.f; }
  float f0r[9], f1r[9];
#pragma unroll
  for (int k = 0; k < 9; k++) { f0r[k] = dw[c * 9 + k]; f1r[k] = dw[(c + 384) * 9 + k]; }
  __syncthreads();
  int cp = (t & 127) * 2;
  int rg = t >> 7;
#pragma unroll
  for (int r = 0; r < 8; r++) {
    int row = rg * 8 + r;
    float a0 = 0.f, b0 = 0.f, a1 = 0.f, b1 = 0.f;
#pragma unroll
    for (int dh = 0; dh < 3; dh++) {
#pragma unroll
      for (int dwi = 0; dwi < 3; dwi++) {
        float w = f0r[dh * 3 + dwi];
        float wv = f1r[dh * 3 + dwi];
        a0 += s0[row + dh][cp + dwi] * w;
        a1 += s0[row + dh][cp + 1 + dwi] * w;
        b0 += s1[row + dh][cp + dwi] * wv;
        b1 += s1[row + dh][cp + 1 + dwi] * wv;
      }
    }
    float o0 = gelu_exact(a0) * b0;
    float o1 = gelu_exact(a1) * b1;
    *(__half2*)&g_gbh[(long)c * 65536 + (h0 + row) * 256 + cp] = __floats2half2_rn(o0, o1);
  }
}

// ---------------- K7: ff_out (384->192) + residual, fp16 MMA -----------------------
// staging: vectorized pixel-quad loads (LDG.64) + PRMT channel-pair packing
__global__ void k7_ffout(float* __restrict__ out) {
  extern __shared__ unsigned sA[];
  __shared__ float sfl2[192 * 34];
  int blk = blockIdx.x;
  int h = blk >> 3;
  int w0 = (blk & 7) * 32;
  int pix0 = h * 256 + w0;
  int t = threadIdx.x;
  for (int idx = t; idx < 1536; idx += 256) {
    int pp = (idx & 7) * 4;          // pixel quad base 0,4,...,28
    int kk = idx >> 3;               // 0..191 (channel pair)
    int c = kk * 2;
    uint2 X = *(const uint2*)&g_gbh[(long)c * 65536 + pix0 + pp];
    uint2 Y = *(const uint2*)&g_gbh[(long)(c + 1) * 65536 + pix0 + pp];
    sA[pp * 196 + kk] = __byte_perm(X.x, Y.x, 0x5410);
    sA[(pp + 1) * 196 + kk] = __byte_perm(X.x, Y.x, 0x7632);
    sA[(pp + 2) * 196 + kk] = __byte_perm(X.y, Y.y, 0x5410);
    sA[(pp + 3) * 196 + kk] = __byte_perm(X.y, Y.y, 0x7632);
  }
  __syncthreads();
  int wa = t >> 5, lane = t & 31;
  int rq = lane >> 2, acol = lane & 3, ccol0 = 2 * acol;
  float acc[3][2][4];
#pragma unroll
  for (int j = 0; j < 3; j++)
#pragma unroll
    for (int mt = 0; mt < 2; mt++)
#pragma unroll
      for (int r = 0; r < 4; r++) acc[j][mt][r] = 0.f;
  for (int kit = 0; kit < 24; kit++) {
    unsigned A[2][4];
#pragma unroll
    for (int mt = 0; mt < 2; mt++) {
      int r = mt * 16 + rq;
      A[mt][0] = sA[r * 196 + kit * 8 + acol];
      A[mt][1] = sA[(r + 8) * 196 + kit * 8 + acol];
      A[mt][2] = sA[r * 196 + kit * 8 + acol + 4];
      A[mt][3] = sA[(r + 8) * 196 + kit * 8 + acol + 4];
    }
#pragma unroll
    for (int j = 0; j < 3; j++) {
      ull wv = g_wp_out[((wa * 3 + j) * 24 + kit) * 32 + lane];
#pragma unroll
      for (int mt = 0; mt < 2; mt++)
        mma_f16(acc[j][mt], A[mt], (unsigned)wv, (unsigned)(wv >> 32));
    }
  }
#pragma unroll
  for (int j = 0; j < 3; j++) {
    int oc = (wa * 3 + j) * 8 + ccol0;
#pragma unroll
    for (int mt = 0; mt < 2; mt++) {
      int r0 = mt * 16 + rq;
      sfl2[oc * 34 + r0] = acc[j][mt][0];
      sfl2[(oc + 1) * 34 + r0] = acc[j][mt][1];
      sfl2[oc * 34 + r0 + 8] = acc[j][mt][2];
      sfl2[(oc + 1) * 34 + r0 + 8] = acc[j][mt][3];
    }
  }
  __syncthreads();
  for (int idx = t; idx < 6144; idx += 256) {
    int oc = idx >> 5, p = idx & 31;
    int gi = oc * 65536 + pix0 + p;
    out[gi] = g_xres[gi] + sfl2[oc * 34 + p];
  }
}

// ---------------- host launcher ----------------------------------------------------
extern "C" void kernel_launch(void* const* d_in, const int* in_sizes, int n_in,
                              void* d_out, int out_size) {
  const float* x    = (const float*)d_in[0];
  const float* ln1w = (const float*)d_in[1];
  const float* ln1b = (const float*)d_in[2];
  const float* ln2w = (const float*)d_in[3];
  const float* ln2b = (const float*)d_in[4];
  const float* wqkv = (const float*)d_in[5];
  const float* w11  = (const float*)d_in[6];
  const float* b11  = (const float*)d_in[7];
  const float* w12  = (const float*)d_in[8];
  const float* b12  = (const float*)d_in[9];
  const float* w2   = (const float*)d_in[10];
  const float* b2   = (const float*)d_in[11];
  const float* c11  = (const float*)d_in[12];
  const float* ffin = (const float*)d_in[13];
  const float* ffdw = (const float*)d_in[14];
  const float* ffou = (const float*)d_in[15];
  float* out = (float*)d_out;

  const int smem1 = 192 * 65 * 4;                 // 49920
  const int smem234 = 13056 * 4;                  // 52224 (sres 192*68 floats)
  const int smem5 = 14848 * 4;                    // 59392
  const int smem7 = 32 * 196 * 4;                 // 25088
  cudaFuncSetAttribute(k1_qkv, cudaFuncAttributeMaxDynamicSharedMemorySize, smem1);
  cudaFuncSetAttribute(k234_fused, cudaFuncAttributeMaxDynamicSharedMemorySize, smem234);
  cudaFuncSetAttribute(k5_ln_ffin, cudaFuncAttributeMaxDynamicSharedMemorySize, smem5);
  cudaFuncSetAttribute(k7_ffout, cudaFuncAttributeMaxDynamicSharedMemorySize, smem7);

  kpos<<<1, 64>>>();
  kpack<<<144, 256>>>(c11, ffin, ffou, w11, w12, w2, wqkv);
  k1_qkv<<<3072, 256, smem1>>>(x, ln1w, ln1b);
  k234_fused<<<1024, 256, smem234>>>(b11, b12, b2, x);
  k5_ln_ffin<<<1024, 256, smem5>>>(ln2w, ln2b);
  {
    dim3 g6(16, 384);
    k6_dw<<<g6, 256>>>(ffdw);
  }
  k7_ffout<<<2048, 256, smem7>>>(out);
}

// round 17
// speedup vs baseline: 1.1108x; 1.0853x over previous
#include <cuda_runtime.h>
#include <cuda_fp16.h>
#include <math.h>

typedef unsigned long long ull;

// ---------------- fp16 MMA helpers -------------------------------------------------
__device__ __forceinline__ unsigned h2pk(float a, float b) {
  __half2 h = __floats2half2_rn(a, b);
  return *(unsigned*)&h;
}
__device__ __forceinline__ void mma_f16(float* c, const unsigned* a, unsigned b0, unsigned b1) {
  asm volatile(
      "mma.sync.aligned.m16n8k16.row.col.f32.f16.f16.f32 "
      "{%0,%1,%2,%3},{%4,%5,%6,%7},{%8,%9},{%0,%1,%2,%3};"
      : "+f"(c[0]), "+f"(c[1]), "+f"(c[2]), "+f"(c[3])
      : "r"(a[0]), "r"(a[1]), "r"(a[2]), "r"(a[3]), "r"(b0), "r"(b1));
}
__device__ __forceinline__ float gelu_exact(float a) {
  return 0.5f * a * (1.f + erff(a * 0.70710678118654752f));
}

// ---------------- static device scratch --------------------------------------------
__device__ float g_pos[64 * 64];
__device__ __half g_qh[3 * 1024 * 4096];
__device__ __half g_ql[3 * 1024 * 4096];
__device__ __half g_kh[3 * 1024 * 4096];
__device__ __half g_kl[3 * 1024 * 4096];
__device__ __half g_vt[3 * 1024 * 4096];
__device__ float g_xres[192 * 65536];
__device__ __half g_hbh[768 * 65536];
__device__ __half g_gbh[384 * 65536];
// packed fp16 weight fragments: [ntile][kit16][lane] -> (b0 | b1<<32)
__device__ ull g_wp_in[96 * 12 * 32];     // ff_in  (K=192, N=768)
__device__ ull g_wp_out[24 * 24 * 32];    // ff_out (K=384, N=192)
__device__ ull g_wp11[3 * 8 * 12 * 32];   // me_w11 (K=192, N=64)
__device__ ull g_wp12[3 * 8 * 12 * 32];   // me_w12
__device__ ull g_wp2[3 * 8 * 4 * 32];     // me_w2  (K=64,  N=64)
__device__ ull g_wpqkv[24 * 4 * 32];      // w_qkv  (K=64,  N=192)
__device__ ull g_wp192[24 * 12 * 32];     // conv11 (K=192, N=192)

// ---------------- K0a: sine positional encoding ------------------------------------
__global__ void kpos() {
  int n = threadIdx.x;
  int i = n >> 3, j = n & 7;
  double scale = 6.283185307179586476925286766559;
  double yv = (double)(i + 1) / (8.0 + 1e-6) * scale;
  double xv = (double)(j + 1) / (8.0 + 1e-6) * scale;
  for (int c = 0; c < 64; c++) {
    double base = (c < 32) ? yv : xv;
    int k = (c < 32) ? c : (c - 32);
    double dt = pow(10000.0, (double)(k >> 1) / 16.0);
    double v = base / dt;
    g_pos[n * 64 + c] = (float)(((k & 1) == 0) ? sin(v) : cos(v));
  }
}

// ---------------- K0b: fp16 fragment packing ---------------------------------------
__global__ void kpack(const float* __restrict__ c11, const float* __restrict__ ffin,
                      const float* __restrict__ ffout, const float* __restrict__ w11,
                      const float* __restrict__ w12, const float* __restrict__ w2,
                      const float* __restrict__ wqkv) {
  int idx = blockIdx.x * 256 + threadIdx.x;
  int lane = idx & 31;
  if (idx < 36864) {  // wp_in [96][12][32], src [o=768][k=192]
    int kit = (idx >> 5) % 12, nt = idx / 384;
    int o = nt * 8 + (lane >> 2), k0 = kit * 16 + (lane & 3) * 2;
    unsigned b0 = h2pk(ffin[o * 192 + k0], ffin[o * 192 + k0 + 1]);
    unsigned b1 = h2pk(ffin[o * 192 + k0 + 8], ffin[o * 192 + k0 + 9]);
    g_wp_in[idx] = (ull)b0 | ((ull)b1 << 32);
  }
  if (idx < 18432) {  // wp_out [24][24][32], src [o=192][k=384]
    int kit = (idx >> 5) % 24, nt = idx / 768;
    int o = nt * 8 + (lane >> 2), k0 = kit * 16 + (lane & 3) * 2;
    unsigned b0 = h2pk(ffout[o * 384 + k0], ffout[o * 384 + k0 + 1]);
    unsigned b1 = h2pk(ffout[o * 384 + k0 + 8], ffout[o * 384 + k0 + 9]);
    g_wp_out[idx] = (ull)b0 | ((ull)b1 << 32);
  }
  if (idx < 9216) {  // wp11/wp12 [3][8][12][32], src [e][k=192][f=64]
    int e = idx / 3072, r = idx % 3072;
    int kit = (r >> 5) % 12, nt = r / 384;
    int f = nt * 8 + (lane >> 2), k0 = kit * 16 + (lane & 3) * 2;
    const float* Wa = w11 + e * 12288;
    const float* Wb = w12 + e * 12288;
    unsigned a0 = h2pk(Wa[k0 * 64 + f], Wa[(k0 + 1) * 64 + f]);
    unsigned a1 = h2pk(Wa[(k0 + 8) * 64 + f], Wa[(k0 + 9) * 64 + f]);
    g_wp11[idx] = (ull)a0 | ((ull)a1 << 32);
    unsigned c0 = h2pk(Wb[k0 * 64 + f], Wb[(k0 + 1) * 64 + f]);
    unsigned c1 = h2pk(Wb[(k0 + 8) * 64 + f], Wb[(k0 + 9) * 64 + f]);
    g_wp12[idx] = (ull)c0 | ((ull)c1 << 32);
  }
  if (idx < 3072) {  // wp2 [3][8][4][32], src [e][k=64][f=64]
    int e = idx / 1024, r = idx % 1024;
    int kit = (r >> 5) % 4, nt = r / 128;
    int f = nt * 8 + (lane >> 2), k0 = kit * 16 + (lane & 3) * 2;
    const float* Wa = w2 + e * 4096;
    unsigned b0 = h2pk(Wa[k0 * 64 + f], Wa[(k0 + 1) * 64 + f]);
    unsigned b1 = h2pk(Wa[(k0 + 8) * 64 + f], Wa[(k0 + 9) * 64 + f]);
    g_wp2[idx] = (ull)b0 | ((ull)b1 << 32);
  }
  if (idx < 3072) {  // wpqkv [24][4][32], src [k=64][n=192]
    int kit = (idx >> 5) % 4, nt = idx / 128;
    int n = nt * 8 + (lane >> 2), k0 = kit * 16 + (lane & 3) * 2;
    unsigned b0 = h2pk(wqkv[k0 * 192 + n], wqkv[(k0 + 1) * 192 + n]);
    unsigned b1 = h2pk(wqkv[(k0 + 8) * 192 + n], wqkv[(k0 + 9) * 192 + n]);
    g_wpqkv[idx] = (ull)b0 | ((ull)b1 << 32);
  }
  if (idx < 9216) {  // wp192 [24][12][32], src [o=192][k=192]
    int kit = (idx >> 5) % 12, nt = idx / 384;
    int o = nt * 8 + (lane >> 2), k0 = kit * 16 + (lane & 3) * 2;
    unsigned b0 = h2pk(c11[o * 192 + k0], c11[o * 192 + k0 + 1]);
    unsigned b1 = h2pk(c11[o * 192 + k0 + 8], c11[o * 192 + k0 + 9]);
    g_wp192[idx] = (ull)b0 | ((ull)b1 << 32);
  }
}

// ---------------- K1: shift+window + LN1 + pos + QKV GEMM (fp16 MMA) ---------------
__global__ void k1_qkv(const float* __restrict__ x, const float* __restrict__ ln1w,
                       const float* __restrict__ ln1b) {
  extern __shared__ float sm1[];
  float* sx = sm1;
  unsigned* snT = (unsigned*)(sm1 + 4160);
  float* sout = sm1;
  __shared__ float smean[64], srstd[64];
  int blk = blockIdx.x;
  int e = blk >> 10, wwin = blk & 1023;
  int wh = wwin >> 5, ww = wwin & 31;
  int t = threadIdx.x;
  // vectorized staging: pixel quads contiguous even under the roll
  for (int idx = t; idx < 1024; idx += 256) {
    int c = idx >> 4, nq = (idx & 15) * 4;
    int i = nq >> 3, j = nq & 7;
    int h0 = (wh * 8 + i + 4) & 255;
    int w0 = (ww * 8 + j + 4) & 255;
    float4 v = *(const float4*)&x[((e * 64 + c) * 256 + h0) * 256 + w0];
    sx[nq * 65 + c] = v.x;
    sx[(nq + 1) * 65 + c] = v.y;
    sx[(nq + 2) * 65 + c] = v.z;
    sx[(nq + 3) * 65 + c] = v.w;
  }
  __syncthreads();
  if (t < 64) {
    int n = t;
    float m = 0.f;
#pragma unroll
    for (int c = 0; c < 64; c++) m += sx[n * 65 + c];
    m *= (1.f / 64.f);
    float v = 0.f;
#pragma unroll
    for (int c = 0; c < 64; c++) { float d = sx[n * 65 + c] - m; v += d * d; }
    v *= (1.f / 64.f);
    smean[n] = m;
    srstd[n] = rsqrtf(v + 1e-5f);
  }
  __syncthreads();
  for (int idx = t; idx < 2048; idx += 256) {
    int n = idx >> 5, kk = idx & 31;
    int c = kk * 2;
    float v0 = (sx[n * 65 + c] - smean[n]) * srstd[n] * ln1w[c] + ln1b[c] + g_pos[n * 64 + c];
    float v1 = (sx[n * 65 + c + 1] - smean[n]) * srstd[n] * ln1w[c + 1] + ln1b[c + 1] + g_pos[n * 64 + c + 1];
    snT[n * 36 + kk] = h2pk(v0, v1);
  }
  __syncthreads();
  int wa = t >> 5, lane = t & 31;
  int rq = lane >> 2, acol = lane & 3, ccol0 = 2 * acol;
  float acc[3][4][4];
#pragma unroll
  for (int j = 0; j < 3; j++)
#pragma unroll
    for (int mt = 0; mt < 4; mt++)
#pragma unroll
      for (int r = 0; r < 4; r++) acc[j][mt][r] = 0.f;
  for (int kit = 0; kit < 4; kit++) {
    unsigned A[4][4];
#pragma unroll
    for (int mt = 0; mt < 4; mt++) {
      int r = mt * 16 + rq;
      A[mt][0] = snT[r * 36 + kit * 8 + acol];
      A[mt][1] = snT[(r + 8) * 36 + kit * 8 + acol];
      A[mt][2] = snT[r * 36 + kit * 8 + acol + 4];
      A[mt][3] = snT[(r + 8) * 36 + kit * 8 + acol + 4];
    }
#pragma unroll
    for (int j = 0; j < 3; j++) {
      ull wv = g_wpqkv[((wa * 3 + j) * 4 + kit) * 32 + lane];
#pragma unroll
      for (int mt = 0; mt < 4; mt++)
        mma_f16(acc[j][mt], A[mt], (unsigned)wv, (unsigned)(wv >> 32));
    }
  }
  __syncthreads();
#pragma unroll
  for (int j = 0; j < 3; j++) {
    int jc = (wa * 3 + j) * 8 + ccol0;
#pragma unroll
    for (int mt = 0; mt < 4; mt++) {
      int r0 = mt * 16 + rq;
      sout[jc * 65 + r0] = acc[j][mt][0];
      sout[(jc + 1) * 65 + r0] = acc[j][mt][1];
      sout[jc * 65 + r0 + 8] = acc[j][mt][2];
      sout[(jc + 1) * 65 + r0 + 8] = acc[j][mt][3];
    }
  }
  __syncthreads();
  long wb = (long)(e * 1024 + wwin);
  // q/k: hi/lo fp16 split, half2-vectorized (channel pairs)
  for (int idx = t; idx < 4096; idx += 256) {
    int ch2 = idx & 7, n = (idx >> 3) & 63, hh = (idx >> 9) & 3, p = idx >> 11;
    int c0 = ch2 * 2;
    float vv0 = sout[(p * 64 + c0 * 4 + hh) * 65 + n];
    float vv1 = sout[(p * 64 + (c0 + 1) * 4 + hh) * 65 + n];
    __half h0 = __float2half_rn(vv0), h1 = __float2half_rn(vv1);
    __half2 hi = __halves2half2(h0, h1);
    __half2 lo = __floats2half2_rn(vv0 - __half2float(h0), vv1 - __half2float(h1));
    long qi = (wb * 4 + hh) * 1024 + n * 16 + c0;
    if (p == 0) {
      *(__half2*)&g_qh[qi] = hi;
      *(__half2*)&g_ql[qi] = lo;
    } else {
      *(__half2*)&g_kh[qi] = hi;
      *(__half2*)&g_kl[qi] = lo;
    }
  }
  // v: fp16 transposed [hh][ch][n], half2-vectorized (key pairs)
  for (int idx = t; idx < 2048; idx += 256) {
    int n2 = idx & 31, co = idx >> 5;
    int hh = co & 3, ch = co >> 2;
    float vv0 = sout[(128 + co) * 65 + 2 * n2];
    float vv1 = sout[(128 + co) * 65 + 2 * n2 + 1];
    *(__half2*)&g_vt[(wb * 4 + hh) * 1024 + ch * 64 + 2 * n2] = __floats2half2_rn(vv0, vv1);
  }
}

// ---------------- K234: fused 3-exposure attention + GEGLU + conv1x1 + residual ----
// dyn smem u32[13056]: sgin[64][100] @0 | sya[64][100] @6400; sres f32 [192][68] aliases.
__device__ __forceinline__ ull maskw(int row, int wh, int ww) {
  ull m = 0ULL;
  if (wh == 31) m |= ((row >> 3) < 4) ? 0xFFFFFFFF00000000ULL : 0x00000000FFFFFFFFULL;
  if (ww == 31) m |= ((row & 7) < 4) ? 0xF0F0F0F0F0F0F0F0ULL : 0x0F0F0F0F0F0F0F0FULL;
  return m;
}

__global__ void __launch_bounds__(256, 2)
k234_fused(const float* __restrict__ b11, const float* __restrict__ b12,
           const float* __restrict__ b2, const float* __restrict__ x) {
  extern __shared__ unsigned smu[];
  unsigned* sgin = smu;          // [64][100]
  unsigned* sya = smu + 6400;    // [64][100] conv A-tile
  float* sres = (float*)smu;     // [192][68] alias; used after conv MMA
  __shared__ unsigned stu[64 * 36];
  int w = blockIdx.x;
  int wh = w >> 5, ww = w & 31;
  const int ekvA_of[3] = {1, 0, 1};
  const int ekvB_of[3] = {2, 2, 0};
  int t = threadIdx.x;
  int wa = t >> 5, lane = t & 31;
  int rq = lane >> 2, acol = lane & 3;
  int slot = wa >> 2, hh = wa & 3;
  for (int e = 0; e < 3; e++) {
    long qb = (long)(e * 1024 + w) * 4096;
    // --- phase1: merged-q copy + attention (both write disjoint sgin regions) ---
    for (int idx = t; idx < 1024; idx += 256) {
      int n = idx >> 4, pr = idx & 15;
      int hh2 = pr >> 2, c2 = (pr & 3) * 4;
      uint2 qv = *(const uint2*)&g_qh[qb + hh2 * 1024 + n * 16 + c2];
      sgin[n * 100 + 64 + pr * 2] = qv.x;
      sgin[n * 100 + 64 + pr * 2 + 1] = qv.y;
    }
    {
      int ekv = slot ? ekvB_of[e] : ekvA_of[e];
      long kb = ((long)(ekv * 1024 + w) * 4 + hh) * 1024;
      long qhb = qb + hh * 1024;
      unsigned Kfh[8][2], Kfl[8][2];
#pragma unroll
      for (int nt = 0; nt < 8; nt++) {
        int row = nt * 8 + rq;
        Kfh[nt][0] = *(const unsigned*)&g_kh[kb + row * 16 + 2 * acol];
        Kfh[nt][1] = *(const unsigned*)&g_kh[kb + row * 16 + 8 + 2 * acol];
        Kfl[nt][0] = *(const unsigned*)&g_kl[kb + row * 16 + 2 * acol];
        Kfl[nt][1] = *(const unsigned*)&g_kl[kb + row * 16 + 8 + 2 * acol];
      }
      unsigned Vf[4][2][2];
#pragma unroll
      for (int kit = 0; kit < 4; kit++)
#pragma unroll
        for (int n2 = 0; n2 < 2; n2++) {
          Vf[kit][n2][0] = *(const unsigned*)&g_vt[kb + (n2 * 8 + rq) * 64 + (kit * 8 + acol) * 2];
          Vf[kit][n2][1] = *(const unsigned*)&g_vt[kb + (n2 * 8 + rq) * 64 + (kit * 8 + 4 + acol) * 2];
        }
#pragma unroll
      for (int mt = 0; mt < 4; mt++) {
        int r0 = mt * 16 + rq;
        unsigned Ah[4], Al[4];
        Ah[0] = *(const unsigned*)&g_qh[qhb + r0 * 16 + 2 * acol];
        Ah[1] = *(const unsigned*)&g_qh[qhb + (r0 + 8) * 16 + 2 * acol];
        Ah[2] = *(const unsigned*)&g_qh[qhb + r0 * 16 + 8 + 2 * acol];
        Ah[3] = *(const unsigned*)&g_qh[qhb + (r0 + 8) * 16 + 8 + 2 * acol];
        Al[0] = *(const unsigned*)&g_ql[qhb + r0 * 16 + 2 * acol];
        Al[1] = *(const unsigned*)&g_ql[qhb + (r0 + 8) * 16 + 2 * acol];
        Al[2] = *(const unsigned*)&g_ql[qhb + r0 * 16 + 8 + 2 * acol];
        Al[3] = *(const unsigned*)&g_ql[qhb + (r0 + 8) * 16 + 8 + 2 * acol];
        float sc[8][4];
#pragma unroll
        for (int nt = 0; nt < 8; nt++) {
#pragma unroll
          for (int r = 0; r < 4; r++) sc[nt][r] = 0.f;
          mma_f16(sc[nt], Ah, Kfh[nt][0], Kfh[nt][1]);
          mma_f16(sc[nt], Ah, Kfl[nt][0], Kfl[nt][1]);
          mma_f16(sc[nt], Al, Kfh[nt][0], Kfh[nt][1]);
        }
        ull m0 = maskw(r0, wh, ww);
        ull m1 = maskw(r0 + 8, wh, ww);
        float sum0 = 0.f, sum1 = 0.f;
        unsigned Pf[4][4];
#pragma unroll
        for (int nt = 0; nt < 8; nt++) {
          int c0 = nt * 8 + 2 * acol;
          float p0 = ((m0 >> c0) & 1) ? 0.f : __expf(sc[nt][0] * 0.125f);
          float p1 = ((m0 >> (c0 + 1)) & 1) ? 0.f : __expf(sc[nt][1] * 0.125f);
          float p2 = ((m1 >> c0) & 1) ? 0.f : __expf(sc[nt][2] * 0.125f);
          float p3 = ((m1 >> (c0 + 1)) & 1) ? 0.f : __expf(sc[nt][3] * 0.125f);
          sum0 += p0 + p1;
          sum1 += p2 + p3;
          Pf[nt >> 1][(nt & 1) ? 2 : 0] = h2pk(p0, p1);
          Pf[nt >> 1][(nt & 1) ? 3 : 1] = h2pk(p2, p3);
        }
        sum0 += __shfl_xor_sync(0xFFFFFFFFu, sum0, 1);
        sum0 += __shfl_xor_sync(0xFFFFFFFFu, sum0, 2);
        sum1 += __shfl_xor_sync(0xFFFFFFFFu, sum1, 1);
        sum1 += __shfl_xor_sync(0xFFFFFFFFu, sum1, 2);
        float inv0 = 1.f / sum0, inv1 = 1.f / sum1;
        float oc[2][4];
#pragma unroll
        for (int n2 = 0; n2 < 2; n2++)
#pragma unroll
          for (int r = 0; r < 4; r++) oc[n2][r] = 0.f;
#pragma unroll
        for (int kit = 0; kit < 4; kit++)
#pragma unroll
          for (int n2 = 0; n2 < 2; n2++)
            mma_f16(oc[n2], Pf[kit], Vf[kit][n2][0], Vf[kit][n2][1]);
#pragma unroll
        for (int n2 = 0; n2 < 2; n2++) {
          int fb = slot * 32 + hh * 8 + n2 * 4 + acol;
          sgin[r0 * 100 + fb] = h2pk(oc[n2][0] * inv0, oc[n2][1] * inv0);
          sgin[(r0 + 8) * 100 + fb] = h2pk(oc[n2][2] * inv1, oc[n2][3] * inv1);
        }
      }
    }
    __syncthreads();
    // ---- GEGLU GEMM1 ----
    float a1[4][4], g1[4][4];
    {
      int o = wa * 8 + 2 * acol;
      float ba0 = b11[e * 64 + o], ba1 = b11[e * 64 + o + 1];
      float bg0 = b12[e * 64 + o], bg1 = b12[e * 64 + o + 1];
#pragma unroll
      for (int mt = 0; mt < 4; mt++) {
        a1[mt][0] = ba0; a1[mt][1] = ba1; a1[mt][2] = ba0; a1[mt][3] = ba1;
        g1[mt][0] = bg0; g1[mt][1] = bg1; g1[mt][2] = bg0; g1[mt][3] = bg1;
      }
    }
    const ull* W11 = g_wp11 + e * 3072 + wa * 12 * 32;
    const ull* W12 = g_wp12 + e * 3072 + wa * 12 * 32;
    for (int kit = 0; kit < 12; kit++) {
      unsigned A[4][4];
#pragma unroll
      for (int mt = 0; mt < 4; mt++) {
        int r = mt * 16 + rq;
        A[mt][0] = sgin[r * 100 + kit * 8 + acol];
        A[mt][1] = sgin[(r + 8) * 100 + kit * 8 + acol];
        A[mt][2] = sgin[r * 100 + kit * 8 + acol + 4];
        A[mt][3] = sgin[(r + 8) * 100 + kit * 8 + acol + 4];
      }
      ull wv1 = W11[kit * 32 + lane];
      ull wv2 = W12[kit * 32 + lane];
#pragma unroll
      for (int mt = 0; mt < 4; mt++) {
        mma_f16(a1[mt], A[mt], (unsigned)wv1, (unsigned)(wv1 >> 32));
        mma_f16(g1[mt], A[mt], (unsigned)wv2, (unsigned)(wv2 >> 32));
      }
    }
#pragma unroll
    for (int mt = 0; mt < 4; mt++) {
      int r0 = mt * 16 + rq;
      stu[r0 * 36 + wa * 4 + acol] = h2pk(gelu_exact(a1[mt][0]) * g1[mt][0],
                                          gelu_exact(a1[mt][1]) * g1[mt][1]);
      stu[(r0 + 8) * 36 + wa * 4 + acol] = h2pk(gelu_exact(a1[mt][2]) * g1[mt][2],
                                                gelu_exact(a1[mt][3]) * g1[mt][3]);
    }
    __syncthreads();
    // ---- GEGLU GEMM2 -> write y directly into conv A-tile (sya) ----
    float y2[4][4];
    {
      int o = wa * 8 + 2 * acol;
      float b0 = b2[e * 64 + o], b1v = b2[e * 64 + o + 1];
#pragma unroll
      for (int mt = 0; mt < 4; mt++) {
        y2[mt][0] = b0; y2[mt][1] = b1v; y2[mt][2] = b0; y2[mt][3] = b1v;
      }
    }
    const ull* W2 = g_wp2 + e * 1024 + wa * 4 * 32;
    for (int kit = 0; kit < 4; kit++) {
      unsigned A[4][4];
#pragma unroll
      for (int mt = 0; mt < 4; mt++) {
        int r = mt * 16 + rq;
        A[mt][0] = stu[r * 36 + kit * 8 + acol];
        A[mt][1] = stu[(r + 8) * 36 + kit * 8 + acol];
        A[mt][2] = stu[r * 36 + kit * 8 + acol + 4];
        A[mt][3] = stu[(r + 8) * 36 + kit * 8 + acol + 4];
      }
      ull wv = W2[kit * 32 + lane];
#pragma unroll
      for (int mt = 0; mt < 4; mt++)
        mma_f16(y2[mt], A[mt], (unsigned)wv, (unsigned)(wv >> 32));
    }
    int kkb = e * 32 + wa * 4 + acol;
#pragma unroll
    for (int mt = 0; mt < 4; mt++) {
      int r0 = mt * 16 + rq;
      sya[r0 * 100 + kkb] = h2pk(y2[mt][0], y2[mt][1]);
      sya[(r0 + 8) * 100 + kkb] = h2pk(y2[mt][2], y2[mt][3]);
    }
    __syncthreads();
  }
  // ---- conv1x1 (192x192) over the assembled y tile ----
  float acc[3][4][4];
#pragma unroll
  for (int j = 0; j < 3; j++)
#pragma unroll
    for (int mt = 0; mt < 4; mt++)
#pragma unroll
      for (int r = 0; r < 4; r++) acc[j][mt][r] = 0.f;
  for (int kit = 0; kit < 12; kit++) {
    unsigned A[4][4];
#pragma unroll
    for (int mt = 0; mt < 4; mt++) {
      int r = mt * 16 + rq;
      A[mt][0] = sya[r * 100 + kit * 8 + acol];
      A[mt][1] = sya[(r + 8) * 100 + kit * 8 + acol];
      A[mt][2] = sya[r * 100 + kit * 8 + acol + 4];
      A[mt][3] = sya[(r + 8) * 100 + kit * 8 + acol + 4];
    }
#pragma unroll
    for (int j = 0; j < 3; j++) {
      ull wv = g_wp192[((wa * 3 + j) * 12 + kit) * 32 + lane];
#pragma unroll
      for (int mt = 0; mt < 4; mt++)
        mma_f16(acc[j][mt], A[mt], (unsigned)wv, (unsigned)(wv >> 32));
    }
  }
  __syncthreads();   // sya fully consumed; sres may alias it now
  int ccol0 = 2 * acol;
#pragma unroll
  for (int j = 0; j < 3; j++) {
    int oc = (wa * 3 + j) * 8 + ccol0;
#pragma unroll
    for (int mt = 0; mt < 4; mt++) {
      int r0 = mt * 16 + rq;
      sres[oc * 68 + r0] = acc[j][mt][0];
      sres[(oc + 1) * 68 + r0] = acc[j][mt][1];
      sres[oc * 68 + r0 + 8] = acc[j][mt][2];
      sres[(oc + 1) * 68 + r0 + 8] = acc[j][mt][3];
    }
  }
  __syncthreads();
  // vectorized residual epilogue: pixel quads are contiguous even under the roll
  for (int idx = t; idx < 3072; idx += 256) {
    int nq = (idx & 15) * 4;      // n quad base: 0,4,...,60
    int oc = idx >> 4;            // 0..191
    int i = nq >> 3, j = nq & 7;  // j in {0,4}; quad never crosses a window row
    int hp = (wh * 8 + i + 4) & 255;
    int wp = (ww * 8 + j + 4) & 255;
    int gi = oc * 65536 + hp * 256 + wp;
    float4 rv = *(const float4*)&x[gi];
    float4 sv = *(const float4*)&sres[oc * 68 + nq];
    *(float4*)&g_xres[gi] = make_float4(sv.x + rv.x, sv.y + rv.y, sv.z + rv.z, sv.w + rv.w);
  }
}

// ---------------- K5: LN2 + ff_in (192->768) fp16 MMA ------------------------------
// dyn f32[14848]: sxn [64][196] @0 (dies) | sxh u32 [64][100] @0 (in-place) | sfl @6400
__global__ void k5_ln_ffin(const float* __restrict__ ln2w, const float* __restrict__ ln2b) {
  extern __shared__ float sm5[];
  float* sxn = sm5;
  unsigned* sxh = (unsigned*)sm5;
  float* sfl = sm5 + 6400;
  __shared__ float red[256], red2[256], smean[64], srstd[64];
  int blk = blockIdx.x;
  int h = blk >> 2;
  int w0 = (blk & 3) * 64;
  int pix0 = h * 256 + w0;
  int t = threadIdx.x;
  for (int idx = t; idx < 12288; idx += 256) {
    int c = idx >> 6, p = idx & 63;
    sxn[p * 196 + c] = g_xres[c * 65536 + pix0 + p];
  }
  __syncthreads();
  {
    int p = t & 63, g = t >> 6;
    float s = 0.f, s2v = 0.f;
    for (int c = g; c < 192; c += 4) { float v = sxn[p * 196 + c]; s += v; s2v += v * v; }
    red[t] = s;
    red2[t] = s2v;
  }
  __syncthreads();
  if (t < 64) {
    float s = red[t] + red[64 + t] + red[128 + t] + red[192 + t];
    float s2v = red2[t] + red2[64 + t] + red2[128 + t] + red2[192 + t];
    float m = s * (1.f / 192.f);
    float var = s2v * (1.f / 192.f) - m * m;
    smean[t] = m;
    srstd[t] = rsqrtf(var + 1e-5f);
  }
  __syncthreads();
  // in-place f32 -> fp16 conversion via register staging (sxh aliases sxn)
  unsigned tmp[24];
#pragma unroll
  for (int k = 0; k < 24; k++) {
    int idx = t + k * 256;
    int p = idx / 96, kk = idx - p * 96;
    int c = kk * 2;
    float v0 = (sxn[p * 196 + c] - smean[p]) * srstd[p] * ln2w[c] + ln2b[c];
    float v1 = (sxn[p * 196 + c + 1] - smean[p]) * srstd[p] * ln2w[c + 1] + ln2b[c + 1];
    tmp[k] = h2pk(v0, v1);
  }
  __syncthreads();
#pragma unroll
  for (int k = 0; k < 24; k++) {
    int idx = t + k * 256;
    int p = idx / 96, kk = idx - p * 96;
    sxh[p * 100 + kk] = tmp[k];
  }
  __syncthreads();
  int wa = t >> 5, lane = t & 31;
  int rq = lane >> 2, acol = lane & 3, ccol0 = 2 * acol;
  for (int ch = 0; ch < 6; ch++) {
    float acc[2][4][4];
#pragma unroll
    for (int j = 0; j < 2; j++)
#pragma unroll
      for (int mt = 0; mt < 4; mt++)
#pragma unroll
        for (int r = 0; r < 4; r++) acc[j][mt][r] = 0.f;
    for (int kit = 0; kit < 12; kit++) {
      unsigned A[4][4];
#pragma unroll
      for (int mt = 0; mt < 4; mt++) {
        int r = mt * 16 + rq;
        A[mt][0] = sxh[r * 100 + kit * 8 + acol];
        A[mt][1] = sxh[(r + 8) * 100 + kit * 8 + acol];
        A[mt][2] = sxh[r * 100 + kit * 8 + acol + 4];
        A[mt][3] = sxh[(r + 8) * 100 + kit * 8 + acol + 4];
      }
#pragma unroll
      for (int j = 0; j < 2; j++) {
        int nt = wa * 12 + ch * 2 + j;
        ull wv = g_wp_in[(nt * 12 + kit) * 32 + lane];
#pragma unroll
        for (int mt = 0; mt < 4; mt++)
          mma_f16(acc[j][mt], A[mt], (unsigned)wv, (unsigned)(wv >> 32));
      }
    }
#pragma unroll
    for (int j = 0; j < 2; j++) {
      int lc = (wa * 2 + j) * 8 + ccol0;
#pragma unroll
      for (int mt = 0; mt < 4; mt++) {
        int r0 = mt * 16 + rq;
        sfl[lc * 66 + r0] = acc[j][mt][0];
        sfl[(lc + 1) * 66 + r0] = acc[j][mt][1];
        sfl[lc * 66 + r0 + 8] = acc[j][mt][2];
        sfl[(lc + 1) * 66 + r0 + 8] = acc[j][mt][3];
      }
    }
    __syncthreads();
    for (int idx = t; idx < 4096; idx += 256) {
      int lc = idx >> 5, p2 = (idx & 31) * 2;
      int o = ((lc >> 4) * 12 + ch * 2 + ((lc >> 3) & 1)) * 8 + (lc & 7);
      *(__half2*)&g_hbh[(long)o * 65536 + pix0 + p2] =
          __floats2half2_rn(sfl[lc * 66 + p2], sfl[lc * 66 + p2 + 1]);
    }
    __syncthreads();
  }
}

// ---------------- K6: depthwise 3x3 + gelu(g1)*g2, vectorized LDG.128 staging ------
__global__ void k6_dw(const float* __restrict__ dw) {
  __shared__ __align__(16) float s0[18][264];
  __shared__ __align__(16) float s1[18][264];
  int h0 = blockIdx.x * 16;
  int c = blockIdx.y;
  int t = threadIdx.x;
  const __half* p0 = g_hbh + (long)c * 65536;
  const __half* p1 = g_hbh + (long)(c + 384) * 65536;
  // interior pixel w stored at column 4+w; halos at columns 3 and 260.
  for (int idx = t; idx < 576; idx += 256) {
    int r = idx >> 5, q = idx & 31;
    int hh = h0 - 1 + r;
    float4 lo0 = make_float4(0.f, 0.f, 0.f, 0.f), hi0 = lo0, lo1 = lo0, hi1 = lo0;
    if (hh >= 0 && hh < 256) {
      uint4 a = *(const uint4*)&p0[hh * 256 + q * 8];
      uint4 b = *(const uint4*)&p1[hh * 256 + q * 8];
      float2 f;
      f = __half22float2(*(__half2*)&a.x); lo0.x = f.x; lo0.y = f.y;
      f = __half22float2(*(__half2*)&a.y); lo0.z = f.x; lo0.w = f.y;
      f = __half22float2(*(__half2*)&a.z); hi0.x = f.x; hi0.y = f.y;
      f = __half22float2(*(__half2*)&a.w); hi0.z = f.x; hi0.w = f.y;
      f = __half22float2(*(__half2*)&b.x); lo1.x = f.x; lo1.y = f.y;
      f = __half22float2(*(__half2*)&b.y); lo1.z = f.x; lo1.w = f.y;
      f = __half22float2(*(__half2*)&b.z); hi1.x = f.x; hi1.y = f.y;
      f = __half22float2(*(__half2*)&b.w); hi1.z = f.x; hi1.w = f.y;
    }
    *(float4*)&s0[r][4 + q * 8] = lo0;
    *(float4*)&s0[r][8 + q * 8] = hi0;
    *(float4*)&s1[r][4 + q * 8] = lo1;
    *(float4*)&s1[r][8 + q * 8] = hi1;
  }
  if (t < 18) { s0[t][3] = 0.f; s0[t][260] = 0.f; s1[t][3] = 0.f; s1[t][260] = 0.f; }
  float f0r[9], f1r[9];
#pragma unroll
  for (int k = 0; k < 9; k++) { f0r[k] = dw[c * 9 + k]; f1r[k] = dw[(c + 384) * 9 + k]; }
  __syncthreads();
  int cp = (t & 127) * 2;
  int rg = t >> 7;
#pragma unroll
  for (int r = 0; r < 8; r++) {
    int row = rg * 8 + r;
    float a0 = 0.f, b0 = 0.f, a1 = 0.f, b1 = 0.f;
#pragma unroll
    for (int dh = 0; dh < 3; dh++) {
#pragma unroll
      for (int dwi = 0; dwi < 3; dwi++) {
        float w = f0r[dh * 3 + dwi];
        float wv = f1r[dh * 3 + dwi];
        a0 += s0[row + dh][3 + cp + dwi] * w;
        a1 += s0[row + dh][4 + cp + dwi] * w;
        b0 += s1[row + dh][3 + cp + dwi] * wv;
        b1 += s1[row + dh][4 + cp + dwi] * wv;
      }
    }
    float o0 = gelu_exact(a0) * b0;
    float o1 = gelu_exact(a1) * b1;
    *(__half2*)&g_gbh[(long)c * 65536 + (h0 + row) * 256 + cp] = __floats2half2_rn(o0, o1);
  }
}

// ---------------- K7: ff_out (384->192) + residual, fp16 MMA -----------------------
// staging: vectorized pixel-quad loads (LDG.64) + PRMT channel-pair packing
__global__ void k7_ffout(float* __restrict__ out) {
  extern __shared__ unsigned sA[];
  __shared__ float sfl2[192 * 34];
  int blk = blockIdx.x;
  int h = blk >> 3;
  int w0 = (blk & 7) * 32;
  int pix0 = h * 256 + w0;
  int t = threadIdx.x;
  for (int idx = t; idx < 1536; idx += 256) {
    int pp = (idx & 7) * 4;          // pixel quad base 0,4,...,28
    int kk = idx >> 3;               // 0..191 (channel pair)
    int c = kk * 2;
    uint2 X = *(const uint2*)&g_gbh[(long)c * 65536 + pix0 + pp];
    uint2 Y = *(const uint2*)&g_gbh[(long)(c + 1) * 65536 + pix0 + pp];
    sA[pp * 196 + kk] = __byte_perm(X.x, Y.x, 0x5410);
    sA[(pp + 1) * 196 + kk] = __byte_perm(X.x, Y.x, 0x7632);
    sA[(pp + 2) * 196 + kk] = __byte_perm(X.y, Y.y, 0x5410);
    sA[(pp + 3) * 196 + kk] = __byte_perm(X.y, Y.y, 0x7632);
  }
  __syncthreads();
  int wa = t >> 5, lane = t & 31;
  int rq = lane >> 2, acol = lane & 3, ccol0 = 2 * acol;
  float acc[3][2][4];
#pragma unroll
  for (int j = 0; j < 3; j++)
#pragma unroll
    for (int mt = 0; mt < 2; mt++)
#pragma unroll
      for (int r = 0; r < 4; r++) acc[j][mt][r] = 0.f;
  for (int kit = 0; kit < 24; kit++) {
    unsigned A[2][4];
#pragma unroll
    for (int mt = 0; mt < 2; mt++) {
      int r = mt * 16 + rq;
      A[mt][0] = sA[r * 196 + kit * 8 + acol];
      A[mt][1] = sA[(r + 8) * 196 + kit * 8 + acol];
      A[mt][2] = sA[r * 196 + kit * 8 + acol + 4];
      A[mt][3] = sA[(r + 8) * 196 + kit * 8 + acol + 4];
    }
#pragma unroll
    for (int j = 0; j < 3; j++) {
      ull wv = g_wp_out[((wa * 3 + j) * 24 + kit) * 32 + lane];
#pragma unroll
      for (int mt = 0; mt < 2; mt++)
        mma_f16(acc[j][mt], A[mt], (unsigned)wv, (unsigned)(wv >> 32));
    }
  }
#pragma unroll
  for (int j = 0; j < 3; j++) {
    int oc = (wa * 3 + j) * 8 + ccol0;
#pragma unroll
    for (int mt = 0; mt < 2; mt++) {
      int r0 = mt * 16 + rq;
      sfl2[oc * 34 + r0] = acc[j][mt][0];
      sfl2[(oc + 1) * 34 + r0] = acc[j][mt][1];
      sfl2[oc * 34 + r0 + 8] = acc[j][mt][2];
      sfl2[(oc + 1) * 34 + r0 + 8] = acc[j][mt][3];
    }
  }
  __syncthreads();
  for (int idx = t; idx < 6144; idx += 256) {
    int oc = idx >> 5, p = idx & 31;
    int gi = oc * 65536 + pix0 + p;
    out[gi] = g_xres[gi] + sfl2[oc * 34 + p];
  }
}

// ---------------- host launcher ----------------------------------------------------
extern "C" void kernel_launch(void* const* d_in, const int* in_sizes, int n_in,
                              void* d_out, int out_size) {
  const float* x    = (const float*)d_in[0];
  const float* ln1w = (const float*)d_in[1];
  const float* ln1b = (const float*)d_in[2];
  const float* ln2w = (const float*)d_in[3];
  const float* ln2b = (const float*)d_in[4];
  const float* wqkv = (const float*)d_in[5];
  const float* w11  = (const float*)d_in[6];
  const float* b11  = (const float*)d_in[7];
  const float* w12  = (const float*)d_in[8];
  const float* b12  = (const float*)d_in[9];
  const float* w2   = (const float*)d_in[10];
  const float* b2   = (const float*)d_in[11];
  const float* c11  = (const float*)d_in[12];
  const float* ffin = (const float*)d_in[13];
  const float* ffdw = (const float*)d_in[14];
  const float* ffou = (const float*)d_in[15];
  float* out = (float*)d_out;

  const int smem1 = 192 * 65 * 4;                 // 49920
  const int smem234 = 13056 * 4;                  // 52224 (sres 192*68 floats)
  const int smem5 = 14848 * 4;                    // 59392
  const int smem7 = 32 * 196 * 4;                 // 25088
  cudaFuncSetAttribute(k1_qkv, cudaFuncAttributeMaxDynamicSharedMemorySize, smem1);
  cudaFuncSetAttribute(k234_fused, cudaFuncAttributeMaxDynamicSharedMemorySize, smem234);
  cudaFuncSetAttribute(k5_ln_ffin, cudaFuncAttributeMaxDynamicSharedMemorySize, smem5);
  cudaFuncSetAttribute(k7_ffout, cudaFuncAttributeMaxDynamicSharedMemorySize, smem7);

  kpos<<<1, 64>>>();
  kpack<<<144, 256>>>(c11, ffin, ffou, w11, w12, w2, wqkv);
  k1_qkv<<<3072, 256, smem1>>>(x, ln1w, ln1b);
  k234_fused<<<1024, 256, smem234>>>(b11, b12, b2, x);
  k5_ln_ffin<<<1024, 256, smem5>>>(ln2w, ln2b);
  {
    dim3 g6(16, 384);
    k6_dw<<<g6, 256>>>(ffdw);
  }
  k7_ffout<<<2048, 256, smem7>>>(out);
}